// round 8
// baseline (speedup 1.0000x reference)
#include <cuda_runtime.h>
#include <math.h>

#define NB 64
#define NN 4096
#define ROWS (NB*NN)          // 262144
#define SCALE 0.125f
#define LN_EPS 1e-5f
#define SUM_EPS 1e-8f

// ---------------- device scratch (no allocations allowed) ----------------
__device__ float g_kv[(size_t)ROWS*512];   // [row][0:256]=k, [256:512]=v  (512MB)
__device__ float g_WT [256*512];           // WT[d][o] : o<256 -> Wk, else Wv
__device__ float g_WqT[256*256];
__device__ float g_WihT[256*768];
__device__ float g_WhhT[256*768];
__device__ float g_mu[ROWS];
__device__ float g_rs[ROWS];
__device__ float g_q[512*256];             // [(b*8+i)][h*64+d], pre-scaled
__device__ float g_attn[(size_t)NB*32*NN]; // [b][ih][j] softmaxed (pre-renorm)
__device__ float g_denom[NB*32];
__device__ float g_upd[512*256];
__device__ float g_slotsA[512*256];
__device__ float g_slotsB[512*256];

// ---------------- f32x2 packed-FMA helpers (Blackwell) ----------------
#define PK2(d,x,y)   asm("mov.b64 %0, {%1,%2};"          : "=l"(d) : "f"(x), "f"(y))
#define UPK2(x,y,d)  asm("mov.b64 {%0,%1}, %2;"          : "=f"(x), "=f"(y) : "l"(d))
#define FMA2(d,a,b,c) asm("fma.rn.f32x2 %0, %1, %2, %3;" : "=l"(d) : "l"(a), "l"(b), "l"(c))

// ---------------- prep: transpose weights ----------------
__global__ void prep_w(const float* __restrict__ Wq, const float* __restrict__ Wk,
                       const float* __restrict__ Wv, const float* __restrict__ wih,
                       const float* __restrict__ whh) {
    int idx = blockIdx.x*256 + threadIdx.x;          // < 196608
    if (idx < 256*512) {
        int d = idx >> 9, o = idx & 511;
        g_WT[idx] = (o < 256) ? Wk[o*256 + d] : Wv[(o-256)*256 + d];
    }
    if (idx < 256*256) {
        int d = idx >> 8, o = idx & 255;
        g_WqT[idx] = Wq[o*256 + d];
    }
    {
        int d = idx / 768, o = idx - d*768;          // idx < 196608 always
        g_WihT[idx] = wih[o*256 + d];
        g_WhhT[idx] = whh[o*256 + d];
    }
}

// ---------------- LayerNorm stats (warp per row) ----------------
__global__ void ln_stats(const float* __restrict__ x) {
    int row  = blockIdx.x*8 + (threadIdx.x >> 5);
    int lane = threadIdx.x & 31;
    const float4* xr = (const float4*)(x + (size_t)row*256);
    float s = 0.f, ss = 0.f;
#pragma unroll
    for (int i = 0; i < 2; i++) {
        float4 v = xr[lane + 32*i];
        s  += v.x + v.y + v.z + v.w;
        ss += v.x*v.x + v.y*v.y + v.z*v.z + v.w*v.w;
    }
#pragma unroll
    for (int o = 16; o; o >>= 1) {
        s  += __shfl_xor_sync(0xffffffffu, s,  o);
        ss += __shfl_xor_sync(0xffffffffu, ss, o);
    }
    if (lane == 0) {
        float mu  = s * (1.f/256.f);
        float var = ss * (1.f/256.f) - mu*mu;
        g_mu[row] = mu;
        g_rs[row] = rsqrtf(var + LN_EPS);
    }
}

// ---------------- fused LN + K/V GEMM: [262144,256] @ [256,512] ----------------
// 128x128 block tile, K-chunks of 16, 8x8 per-thread micro-tile, f32x2 FMAs.
__global__ void __launch_bounds__(256,2)
kv_gemm(const float* __restrict__ x, const float* __restrict__ lw,
        const float* __restrict__ lb) {
    __shared__ float As[16][128];
    __shared__ float Bs[16][128];

    int tid = threadIdx.x;
    int m0 = blockIdx.y * 128, c0 = blockIdx.x * 128;

    int mA0 = tid >> 2;                  // 0..63
    int kq  = (tid & 3) * 4;             // 0,4,8,12
    float mu0 = g_mu[m0+mA0],    rs0 = g_rs[m0+mA0];
    float mu1 = g_mu[m0+mA0+64], rs1 = g_rs[m0+mA0+64];

    int r8 = (tid >> 4) * 8;             // row of micro-tile
    int c8 = (tid & 15) * 8;             // col of micro-tile

    unsigned long long acc[8][4];
#pragma unroll
    for (int i = 0; i < 8; i++)
#pragma unroll
        for (int p = 0; p < 4; p++) acc[i][p] = 0ull;

    for (int kc = 0; kc < 16; kc++) {
        int k0 = kc * 16;
        float4 w4 = *(const float4*)&lw[k0 + kq];
        float4 b4 = *(const float4*)&lb[k0 + kq];
        float4 xa = *(const float4*)&x[(size_t)(m0+mA0)   *256 + k0 + kq];
        float4 xb = *(const float4*)&x[(size_t)(m0+mA0+64)*256 + k0 + kq];
        float4 bt0 = *(const float4*)&g_WT[(k0 +     (tid>>5))*512 + c0 + (tid&31)*4];
        float4 bt1 = *(const float4*)&g_WT[(k0 + 8 + (tid>>5))*512 + c0 + (tid&31)*4];

        __syncthreads();
        As[kq+0][mA0]    = (xa.x - mu0)*rs0*w4.x + b4.x;
        As[kq+1][mA0]    = (xa.y - mu0)*rs0*w4.y + b4.y;
        As[kq+2][mA0]    = (xa.z - mu0)*rs0*w4.z + b4.z;
        As[kq+3][mA0]    = (xa.w - mu0)*rs0*w4.w + b4.w;
        As[kq+0][mA0+64] = (xb.x - mu1)*rs1*w4.x + b4.x;
        As[kq+1][mA0+64] = (xb.y - mu1)*rs1*w4.y + b4.y;
        As[kq+2][mA0+64] = (xb.z - mu1)*rs1*w4.z + b4.z;
        As[kq+3][mA0+64] = (xb.w - mu1)*rs1*w4.w + b4.w;
        *(float4*)&Bs[    (tid>>5)][(tid&31)*4] = bt0;
        *(float4*)&Bs[8 + (tid>>5)][(tid&31)*4] = bt1;
        __syncthreads();

#pragma unroll
        for (int kk = 0; kk < 16; kk++) {
            float4 a0 = *(const float4*)&As[kk][r8];
            float4 a1 = *(const float4*)&As[kk][r8+4];
            float4 b0 = *(const float4*)&Bs[kk][c8];
            float4 b1 = *(const float4*)&Bs[kk][c8+4];
            unsigned long long bp0, bp1, bp2, bp3;
            PK2(bp0, b0.x, b0.y); PK2(bp1, b0.z, b0.w);
            PK2(bp2, b1.x, b1.y); PK2(bp3, b1.z, b1.w);
            float av[8] = {a0.x,a0.y,a0.z,a0.w,a1.x,a1.y,a1.z,a1.w};
#pragma unroll
            for (int i = 0; i < 8; i++) {
                unsigned long long ap;
                PK2(ap, av[i], av[i]);
                FMA2(acc[i][0], ap, bp0, acc[i][0]);
                FMA2(acc[i][1], ap, bp1, acc[i][1]);
                FMA2(acc[i][2], ap, bp2, acc[i][2]);
                FMA2(acc[i][3], ap, bp3, acc[i][3]);
            }
        }
    }

#pragma unroll
    for (int i = 0; i < 8; i++) {
        float4 o0, o1;
        UPK2(o0.x, o0.y, acc[i][0]); UPK2(o0.z, o0.w, acc[i][1]);
        UPK2(o1.x, o1.y, acc[i][2]); UPK2(o1.z, o1.w, acc[i][3]);
        size_t base = (size_t)(m0 + r8 + i)*512 + c0 + c8;
        *(float4*)&g_kv[base]     = o0;
        *(float4*)&g_kv[base + 4] = o1;
    }
}

// ---------------- slot LN + q projection (+ zero denom) ----------------
__global__ void __launch_bounds__(256)
slot_q(int it, const float* __restrict__ cond,
       const float* __restrict__ lw, const float* __restrict__ lb) {
    const float* src = (it == 0) ? cond : (it == 1 ? g_slotsA : g_slotsB);
    int row = blockIdx.x, t = threadIdx.x;
    float v = src[row*256 + t];
    float s = v, ss = v*v;
#pragma unroll
    for (int o = 16; o; o >>= 1) {
        s  += __shfl_xor_sync(0xffffffffu, s,  o);
        ss += __shfl_xor_sync(0xffffffffu, ss, o);
    }
    __shared__ float ps[8], pss[8];
    __shared__ float smu, srs;
    __shared__ float sn[256];
    if ((t & 31) == 0) { ps[t>>5] = s; pss[t>>5] = ss; }
    __syncthreads();
    if (t == 0) {
        float S = 0.f, SS = 0.f;
#pragma unroll
        for (int i = 0; i < 8; i++) { S += ps[i]; SS += pss[i]; }
        float mu = S * (1.f/256.f);
        smu = mu;
        srs = rsqrtf(SS * (1.f/256.f) - mu*mu + LN_EPS);
    }
    if (t < 4) g_denom[row*4 + t] = 0.f;   // denom[b][i*4+h] == [row*4+h]
    __syncthreads();
    sn[t] = (v - smu)*srs*lw[t] + lb[t];
    __syncthreads();
    float acc = 0.f;
#pragma unroll 4
    for (int d = 0; d < 256; d++) acc += sn[d] * g_WqT[d*256 + t];
    g_q[row*256 + t] = acc * SCALE;
}

// ---------------- dots + 32-way softmax + denom + outputs ----------------
// Grid: (128 j-tiles, 64 b). Block: 8 warps, each warp handles 4 j's.
__global__ void __launch_bounds__(256)
dots_softmax(float* __restrict__ out_stack, float* __restrict__ out_last) {
    int b = blockIdx.y, jt = blockIdx.x;
    int j0 = jt * 32;
    int tid = threadIdx.x, w = tid >> 5, lane = tid & 31;
    int hl = lane >> 3, dsub = lane & 7;

    __shared__ float qs[2048];
    __shared__ float attn_s[32][33];
    __shared__ float stk_s[8][33];
    __shared__ float den_s[32];

    if (tid < 16) g_upd[(b*128 + jt)*16 + tid] = 0.f;   // distributed zeroing
    if (tid < 32) den_s[tid] = 0.f;
#pragma unroll
    for (int r = 0; r < 8; r++) qs[r*256 + tid] = g_q[b*2048 + r*256 + tid];
    __syncthreads();

    unsigned long long qp[8][4];
#pragma unroll
    for (int i = 0; i < 8; i++)
#pragma unroll
        for (int p = 0; p < 4; p++) {
            int base = i*256 + hl*64 + dsub*8 + p*2;
            PK2(qp[i][p], qs[base], qs[base+1]);
        }

    float dsum[8];
#pragma unroll
    for (int i = 0; i < 8; i++) dsum[i] = 0.f;

    for (int jj = 0; jj < 4; jj++) {
        int j = j0 + w*4 + jj;
        const float4* krow = (const float4*)&g_kv[(size_t)(b*NN + j)*512];
        float4 k0 = krow[lane*2], k1 = krow[lane*2 + 1];
        unsigned long long kp[4];
        PK2(kp[0], k0.x, k0.y); PK2(kp[1], k0.z, k0.w);
        PK2(kp[2], k1.x, k1.y); PK2(kp[3], k1.z, k1.w);

        float part[8];
#pragma unroll
        for (int i = 0; i < 8; i++) {
            unsigned long long a = 0ull;
            FMA2(a, qp[i][0], kp[0], a);
            FMA2(a, qp[i][1], kp[1], a);
            FMA2(a, qp[i][2], kp[2], a);
            FMA2(a, qp[i][3], kp[3], a);
            float x0, x1; UPK2(x0, x1, a);
            part[i] = x0 + x1;
        }
#pragma unroll
        for (int i = 0; i < 8; i++) {
            part[i] += __shfl_xor_sync(0xffffffffu, part[i], 1);
            part[i] += __shfl_xor_sync(0xffffffffu, part[i], 2);
            part[i] += __shfl_xor_sync(0xffffffffu, part[i], 4);
        }
        float mx = part[0];
#pragma unroll
        for (int i = 1; i < 8; i++) mx = fmaxf(mx, part[i]);
        mx = fmaxf(mx, __shfl_xor_sync(0xffffffffu, mx, 8));
        mx = fmaxf(mx, __shfl_xor_sync(0xffffffffu, mx, 16));
        float e[8], ssum = 0.f;
#pragma unroll
        for (int i = 0; i < 8; i++) { e[i] = __expf(part[i] - mx); ssum += e[i]; }
        ssum += __shfl_xor_sync(0xffffffffu, ssum, 8);
        ssum += __shfl_xor_sync(0xffffffffu, ssum, 16);
        float inv = 1.f / ssum;
#pragma unroll
        for (int i = 0; i < 8; i++) e[i] *= inv;
        float ms[8];
#pragma unroll
        for (int i = 0; i < 8; i++) {
            float tv = e[i];
            tv += __shfl_xor_sync(0xffffffffu, tv, 8);
            tv += __shfl_xor_sync(0xffffffffu, tv, 16);
            ms[i] = tv;
        }
        if (dsub == 0) {
            int jloc = w*4 + jj;
#pragma unroll
            for (int i = 0; i < 8; i++) { attn_s[i*4 + hl][jloc] = e[i]; dsum[i] += e[i]; }
            if (hl == 0) {
#pragma unroll
                for (int i = 0; i < 8; i++) stk_s[i][jloc] = ms[i] * 0.25f;
            }
        }
    }

    if (dsub == 0) {
#pragma unroll
        for (int i = 0; i < 8; i++) atomicAdd(&den_s[i*4 + hl], dsum[i]);
    }
    __syncthreads();
    if (tid < 32) atomicAdd(&g_denom[b*32 + tid], den_s[tid]);

#pragma unroll
    for (int r = 0; r < 4; r++) {
        int idx = r*256 + tid; int ih = idx >> 5, jc = idx & 31;
        g_attn[(size_t)(b*32 + ih)*NN + j0 + jc] = attn_s[ih][jc];
    }
    {
        int i = tid >> 5, jc = tid & 31;
        float v = stk_s[i][jc];
        size_t o = (size_t)(b*8 + i)*NN + j0 + jc;
        out_stack[o] = v;
        if (out_last) out_last[o] = v;
    }
}

// ---------------- updates = (attn/denom) @ v ----------------
// Grid: (4 j-chunks, 4 heads, 64 b). 1024 j per chunk.
__global__ void __launch_bounds__(256)
upd_kernel() {
    int chunk = blockIdx.x, h = blockIdx.y, b = blockIdx.z;
    int tid = threadIdx.x;
    int d = tid & 63, js = tid >> 6;
    __shared__ float at_s[8][128];
    __shared__ float dinv[8];
    if (tid < 8) dinv[tid] = 1.f / (g_denom[b*32 + tid*4 + h] + SUM_EPS);
    float acc[8];
#pragma unroll
    for (int i = 0; i < 8; i++) acc[i] = 0.f;
    int j0 = chunk * 1024;
    for (int sc = 0; sc < 8; sc++) {
        __syncthreads();
#pragma unroll
        for (int r = 0; r < 4; r++) {
            int idx = r*256 + tid; int i = idx >> 7, jc = idx & 127;
            at_s[i][jc] = g_attn[(size_t)(b*32 + i*4 + h)*NN + j0 + sc*128 + jc];
        }
        __syncthreads();
#pragma unroll 4
        for (int jj = 0; jj < 32; jj++) {
            int jl = jj*4 + js;
            float vv = g_kv[(size_t)(b*NN + j0 + sc*128 + jl)*512 + 256 + h*64 + d];
#pragma unroll
            for (int i = 0; i < 8; i++) acc[i] += vv * at_s[i][jl];
        }
    }
#pragma unroll
    for (int i = 0; i < 8; i++)
        atomicAdd(&g_upd[(b*8 + i)*256 + h*64 + d], acc[i] * dinv[i]);
}

// ---------------- GRU cell (4 rows per block for weight reuse) ----------------
__global__ void __launch_bounds__(256)
gru_kernel(int it, const float* __restrict__ cond, float* __restrict__ out_slots,
           const float* __restrict__ bih, const float* __restrict__ bhh) {
    const float* hsrc = (it == 0) ? cond : (it == 1 ? g_slotsA : g_slotsB);
    float* dst = (it == 0) ? g_slotsA : (it == 1 ? g_slotsB : out_slots);
    int t = threadIdx.x;
    __shared__ float u_s[4][256], h_s[4][256];
#pragma unroll
    for (int r = 0; r < 4; r++) {
        int row = blockIdx.x*4 + r;
        u_s[r][t] = g_upd[row*256 + t];
        h_s[r][t] = hsrc[row*256 + t];
    }
    __syncthreads();
    float axr[4] = {0,0,0,0}, axz[4] = {0,0,0,0}, axn[4] = {0,0,0,0};
    float ahr[4] = {0,0,0,0}, ahz[4] = {0,0,0,0}, ahn[4] = {0,0,0,0};
#pragma unroll 2
    for (int dd = 0; dd < 256; dd++) {
        float wr = g_WihT[dd*768 + t],       wz = g_WihT[dd*768 + 256 + t];
        float wn = g_WihT[dd*768 + 512 + t];
        float vr = g_WhhT[dd*768 + t],       vz = g_WhhT[dd*768 + 256 + t];
        float vn = g_WhhT[dd*768 + 512 + t];
#pragma unroll
        for (int r = 0; r < 4; r++) {
            float u = u_s[r][dd], hh = h_s[r][dd];
            axr[r] += u*wr;  axz[r] += u*wz;  axn[r] += u*wn;
            ahr[r] += hh*vr; ahz[r] += hh*vz; ahn[r] += hh*vn;
        }
    }
    float br = bih[t], bz = bih[256 + t], bn = bih[512 + t];
    float cr = bhh[t], cz = bhh[256 + t], cn = bhh[512 + t];
#pragma unroll
    for (int r = 0; r < 4; r++) {
        float rg = 1.f / (1.f + __expf(-(axr[r] + ahr[r] + br + cr)));
        float zg = 1.f / (1.f + __expf(-(axz[r] + ahz[r] + bz + cz)));
        float ng = tanhf(axn[r] + bn + rg*(ahn[r] + cn));
        int row = blockIdx.x*4 + r;
        dst[row*256 + t] = (1.f - zg)*ng + zg*h_s[r][t];
    }
}

// ---------------- launch ----------------
extern "C" void kernel_launch(void* const* d_in, const int* in_sizes, int n_in,
                              void* d_out, int out_size) {
    (void)in_sizes; (void)n_in; (void)out_size;
    const float* x    = (const float*)d_in[0];
    const float* cond = (const float*)d_in[1];
    const float* lniw = (const float*)d_in[2];
    const float* lnib = (const float*)d_in[3];
    const float* lnsw = (const float*)d_in[4];
    const float* lnsb = (const float*)d_in[5];
    const float* Wq   = (const float*)d_in[6];
    const float* Wk   = (const float*)d_in[7];
    const float* Wv   = (const float*)d_in[8];
    const float* wih  = (const float*)d_in[9];
    const float* whh  = (const float*)d_in[10];
    const float* bih  = (const float*)d_in[11];
    const float* bhh  = (const float*)d_in[12];

    float* out       = (float*)d_out;
    float* out_slots = out;                       // [64,8,256]   = 131072
    float* out_last  = out + 131072;              // [64,8,4096]  = 2097152
    float* out_stack = out + 131072 + 2097152;    // [3,64,8,4096]

    prep_w<<<768, 256>>>(Wq, Wk, Wv, wih, whh);
    ln_stats<<<ROWS/8, 256>>>(x);
    kv_gemm<<<dim3(4, 2048), 256>>>(x, lniw, lnib);

    for (int it = 0; it < 3; it++) {
        slot_q<<<512, 256>>>(it, cond, lnsw, lnsb);
        dots_softmax<<<dim3(128, 64), 256>>>(out_stack + (size_t)it*2097152,
                                             (it == 2) ? out_last : (float*)0);
        upd_kernel<<<dim3(4, 4, 64), 256>>>();
        gru_kernel<<<128, 256>>>(it, cond, out_slots, bih, bhh);
    }
}

// round 11
// speedup vs baseline: 1.4327x; 1.4327x over previous
#include <cuda_runtime.h>
#include <cuda_bf16.h>
#include <math.h>

#define NB 64
#define NN 4096
#define ROWS (NB*NN)          // 262144
#define SCALE 0.125f
#define LN_EPS 1e-5f
#define SUM_EPS 1e-8f

// ---------------- device scratch (no allocations allowed) ----------------
__device__ float g_kv[(size_t)ROWS*512];   // [row][0:256]=k, [256:512]=v
__device__ float g_WqT[256*256];
__device__ float g_WihT[256*768];
__device__ float g_WhhT[256*768];
__device__ float g_mu[ROWS];
__device__ float g_rs[ROWS];
__device__ float g_q[512*256];             // [(b*8+i)][h*64+d], pre-scaled
__device__ float g_attn[(size_t)NB*32*NN]; // [b][ih][j] softmaxed (pre-renorm)
__device__ float g_denom[NB*32];
__device__ float g_upd[512*256];
__device__ float g_slotsA[512*256];
__device__ float g_slotsB[512*256];
// plain row-major bf16 hi/lo images of Wk|Wv: [o in 0..511][k in 0..255]
__device__ __align__(16) unsigned short g_Bhi_img[512*256];
__device__ __align__(16) unsigned short g_Blo_img[512*256];

// ---------------- f32x2 packed-FMA helpers (Blackwell) ----------------
#define PK2(d,x,y)   asm("mov.b64 %0, {%1,%2};"          : "=l"(d) : "f"(x), "f"(y))
#define UPK2(x,y,d)  asm("mov.b64 {%0,%1}, %2;"          : "=f"(x), "=f"(y) : "l"(d))
#define FMA2(d,a,b,c) asm("fma.rn.f32x2 %0, %1, %2, %3;" : "=l"(d) : "l"(a), "l"(b), "l"(c))

// ---------------- baseline-PTX tensor-core helpers (sm_80+) ----------------
__device__ __forceinline__ unsigned smem_u32(const void* p) {
    unsigned a;
    asm("{ .reg .u64 t; cvta.to.shared.u64 t, %1; cvt.u32.u64 %0, t; }" : "=r"(a) : "l"(p));
    return a;
}
#define LDSM4(r, a) \
    asm volatile("ldmatrix.sync.aligned.m8n8.x4.shared.b16 {%0,%1,%2,%3}, [%4];" \
        : "=r"((r)[0]), "=r"((r)[1]), "=r"((r)[2]), "=r"((r)[3]) : "r"(a))
#define MMA16816(d, a, b) \
    asm volatile("mma.sync.aligned.m16n8k16.row.col.f32.bf16.bf16.f32 " \
        "{%0,%1,%2,%3},{%4,%5,%6,%7},{%8,%9},{%0,%1,%2,%3};" \
        : "+f"((d)[0]), "+f"((d)[1]), "+f"((d)[2]), "+f"((d)[3]) \
        : "r"((a)[0]), "r"((a)[1]), "r"((a)[2]), "r"((a)[3]), "r"((b)[0]), "r"((b)[1]))
#define CP_ASYNC16(dst, src) \
    asm volatile("cp.async.cg.shared.global [%0], [%1], 16;" :: "r"(dst), "l"(src))
#define CP_COMMIT() asm volatile("cp.async.commit_group;" ::: "memory")
#define CP_WAIT1()  asm volatile("cp.async.wait_group 1;"  ::: "memory")
#define CP_WAIT0()  asm volatile("cp.async.wait_group 0;"  ::: "memory")

// ---------------- prep: transpose weights (Wq / GRU) ----------------
__global__ void prep_w(const float* __restrict__ Wq, const float* __restrict__ wih,
                       const float* __restrict__ whh) {
    int idx = blockIdx.x*256 + threadIdx.x;          // < 196608
    if (idx < 256*256) {
        int d = idx >> 8, o = idx & 255;
        g_WqT[idx] = Wq[o*256 + d];
    }
    {
        int d = idx / 768, o = idx - d*768;
        g_WihT[idx] = wih[o*256 + d];
        g_WhhT[idx] = whh[o*256 + d];
    }
}

// ---------------- prep: bf16 hi/lo split of Wk|Wv (plain row-major) --------
__global__ void prep_b(const float* __restrict__ Wk, const float* __restrict__ Wv) {
    int o = blockIdx.x, k = threadIdx.x;
    float w = (o < 256) ? Wk[o*256 + k] : Wv[(o-256)*256 + k];
    __nv_bfloat16 hi = __float2bfloat16(w);
    __nv_bfloat16 lo = __float2bfloat16(w - __bfloat162float(hi));
    g_Bhi_img[o*256 + k] = __bfloat16_as_ushort(hi);
    g_Blo_img[o*256 + k] = __bfloat16_as_ushort(lo);
}

// ---------------- LayerNorm stats (warp per row) ----------------
__global__ void ln_stats(const float* __restrict__ x) {
    int row  = blockIdx.x*8 + (threadIdx.x >> 5);
    int lane = threadIdx.x & 31;
    const float4* xr = (const float4*)(x + (size_t)row*256);
    float s = 0.f, ss = 0.f;
#pragma unroll
    for (int i = 0; i < 2; i++) {
        float4 v = xr[lane + 32*i];
        s  += v.x + v.y + v.z + v.w;
        ss += v.x*v.x + v.y*v.y + v.z*v.z + v.w*v.w;
    }
#pragma unroll
    for (int o = 16; o; o >>= 1) {
        s  += __shfl_xor_sync(0xffffffffu, s,  o);
        ss += __shfl_xor_sync(0xffffffffu, ss, o);
    }
    if (lane == 0) {
        float mu  = s * (1.f/256.f);
        float var = ss * (1.f/256.f) - mu*mu;
        g_mu[row] = mu;
        g_rs[row] = rsqrtf(var + LN_EPS);
    }
}

// ---------------- HMMA K/V GEMM: [262144,256] @ [256,512], 3x bf16-split ----
// CTA = 128 rows x 512 outputs. A (hi+lo) resident in smem; B streamed in 16
// chunks (nb 0..7 x k-half 0..1) of 32KB each via cp.async double buffering.
// smem map: A_hi [0,64K) A_lo [64K,128K) Bbuf0 [128K,160K) Bbuf1 [160K,192K)
#define KV_SMEM 196608

__global__ void __launch_bounds__(256, 1)
kv_hmma(const float* __restrict__ x, const float* __restrict__ lw,
        const float* __restrict__ lb) {
    extern __shared__ char smem[];
    __shared__ float smu[128], srs[128];

    const unsigned sb  = smem_u32(smem);
    const unsigned sbB = sb + 131072u;
    int tid = threadIdx.x, wid = tid >> 5, lane = tid & 31;
    int m0 = blockIdx.x * 128;

    if (tid < 128) { smu[tid] = g_mu[m0 + tid]; srs[tid] = g_rs[m0 + tid]; }

    // ---- prefetch B chunk 0 into buffer 0 ----
    {
#pragma unroll
        for (int it = 0; it < 8; it++) {
            int u = tid + it*256;
            int split = u >> 10, rem = u & 1023;
            int o = rem >> 4, g = rem & 15;
            const char* img = split ? (const char*)g_Blo_img : (const char*)g_Bhi_img;
            const char* src = img + (size_t)o*512 + g*16;    // nb=0, half=0
            unsigned dst = sbB + split*16384 + o*256 + ((unsigned)(g ^ (o & 7)) << 4);
            CP_ASYNC16(dst, src);
        }
        CP_COMMIT();
    }
    __syncthreads();   // smu/srs visible

    // ---- load A with fused LN, split into bf16 hi/lo, swizzled ----
    {
        int cpair = tid & 127;            // column pair index
        int c2 = cpair * 2;
        int rbase = (tid >> 7) * 64;
        float w0 = lw[c2], w1 = lw[c2+1], bb0 = lb[c2], bb1 = lb[c2+1];
        unsigned gA = (unsigned)(cpair >> 2);
        unsigned boff = (unsigned)(cpair & 3) * 4u;
#pragma unroll 4
        for (int r = 0; r < 64; r++) {
            int row = rbase + r;
            float2 xv = *(const float2*)&x[(size_t)(m0 + row)*256 + c2];
            float mu = smu[row], rs = srs[row];
            float v0 = (xv.x - mu)*rs*w0 + bb0;
            float v1 = (xv.y - mu)*rs*w1 + bb1;
            __nv_bfloat16 h0 = __float2bfloat16(v0);
            __nv_bfloat16 h1 = __float2bfloat16(v1);
            __nv_bfloat16 l0 = __float2bfloat16(v0 - __bfloat162float(h0));
            __nv_bfloat16 l1 = __float2bfloat16(v1 - __bfloat162float(h1));
            unsigned hp = (unsigned)__bfloat16_as_ushort(h0) |
                          ((unsigned)__bfloat16_as_ushort(h1) << 16);
            unsigned lp = (unsigned)__bfloat16_as_ushort(l0) |
                          ((unsigned)__bfloat16_as_ushort(l1) << 16);
            unsigned phys = (unsigned)row*512u + ((gA ^ (unsigned)(row & 7)) << 4) + boff;
            *(unsigned*)(smem + phys)          = hp;
            *(unsigned*)(smem + 65536 + phys)  = lp;
        }
    }

    // ---- warp tiling: 4 M-warps x 2 N-warps, warp tile m32 x n32 ----
    int mw = wid >> 1, nw = wid & 1;
    int rA0 = mw*32 + (lane & 15);                       // ldmatrix A lane row, mtile0
    int rA1 = rA0 + 16;
    unsigned klA = (unsigned)(lane >> 4);                // A k-granule low bit
    unsigned xA = (unsigned)(rA0 & 7);                   // same for rA1
    unsigned aBase0 = sb + (unsigned)rA0*512u;
    unsigned aBase1 = sb + (unsigned)rA1*512u;

    int nB0 = nw*32 + (lane & 7) + ((lane >> 4) & 1)*8;  // ldmatrix B lane row (n index)
    int nB1 = nB0 + 16;
    unsigned kbB = (unsigned)((lane >> 3) & 1);          // B k-granule low bit
    unsigned xB = (unsigned)(nB0 & 7);

    float acc[2][4][4];
#pragma unroll
    for (int i = 0; i < 2; i++)
#pragma unroll
        for (int j = 0; j < 4; j++)
#pragma unroll
            for (int q = 0; q < 4; q++) acc[i][j][q] = 0.f;

    for (int c = 0; c < 16; c++) {
        // prefetch chunk c+1 into the other buffer
        if (c + 1 < 16) {
            int nbn = (c + 1) >> 1, halfn = (c + 1) & 1;
            unsigned bufn = sbB + (unsigned)((c + 1) & 1)*32768u;
#pragma unroll
            for (int it = 0; it < 8; it++) {
                int u = tid + it*256;
                int split = u >> 10, rem = u & 1023;
                int o = rem >> 4, g = rem & 15;
                const char* img = split ? (const char*)g_Blo_img : (const char*)g_Bhi_img;
                const char* src = img + (size_t)(nbn*64 + o)*512 + halfn*256 + g*16;
                unsigned dst = bufn + split*16384 + o*256 + ((unsigned)(g ^ (o & 7)) << 4);
                CP_ASYNC16(dst, src);
            }
            CP_COMMIT();
            CP_WAIT1();
        } else {
            CP_WAIT0();
        }
        __syncthreads();   // chunk c ready in buf c&1; also A ready on first iter

        unsigned buf = sbB + (unsigned)(c & 1)*32768u;
        int half = c & 1;

#pragma unroll
        for (int ks = 0; ks < 8; ks++) {
            unsigned kgA = (unsigned)(half*8 + ks)*2u + klA;
            unsigned aoff = ((kgA ^ xA) << 4);
            unsigned Ahi0[4], Ahi1[4], Alo0[4], Alo1[4];
            LDSM4(Ahi0, aBase0 + aoff);
            LDSM4(Ahi1, aBase1 + aoff);
            LDSM4(Alo0, aBase0 + 65536u + aoff);
            LDSM4(Alo1, aBase1 + 65536u + aoff);

            unsigned kgB = (unsigned)ks*2u + kbB;
            unsigned b0off = (unsigned)nB0*256u + ((kgB ^ xB) << 4);
            unsigned b1off = (unsigned)nB1*256u + ((kgB ^ xB) << 4);
            unsigned Bh[8], Bl[8];
            LDSM4(&Bh[0], buf + b0off);
            LDSM4(&Bh[4], buf + b1off);
            LDSM4(&Bl[0], buf + 16384u + b0off);
            LDSM4(&Bl[4], buf + 16384u + b1off);

#pragma unroll
            for (int j = 0; j < 4; j++) {
                MMA16816(acc[0][j], Ahi0, &Bh[j*2]);
                MMA16816(acc[1][j], Ahi1, &Bh[j*2]);
            }
#pragma unroll
            for (int j = 0; j < 4; j++) {
                MMA16816(acc[0][j], Ahi0, &Bl[j*2]);
                MMA16816(acc[1][j], Ahi1, &Bl[j*2]);
            }
#pragma unroll
            for (int j = 0; j < 4; j++) {
                MMA16816(acc[0][j], Alo0, &Bh[j*2]);
                MMA16816(acc[1][j], Alo1, &Bh[j*2]);
            }
        }

        if (c & 1) {
            // n-block (c>>1) complete: write out and reset accumulators
            int nbidx = c >> 1;
#pragma unroll
            for (int i = 0; i < 2; i++) {
#pragma unroll
                for (int j = 0; j < 4; j++) {
                    int row = m0 + mw*32 + i*16 + (lane >> 2);
                    int col = nbidx*64 + nw*32 + j*8 + (lane & 3)*2;
                    float2 o0 = {acc[i][j][0], acc[i][j][1]};
                    float2 o1 = {acc[i][j][2], acc[i][j][3]};
                    *(float2*)&g_kv[(size_t)row*512 + col]       = o0;
                    *(float2*)&g_kv[(size_t)(row + 8)*512 + col] = o1;
                    acc[i][j][0] = acc[i][j][1] = acc[i][j][2] = acc[i][j][3] = 0.f;
                }
            }
        }
        __syncthreads();   // everyone done with buf c&1 before it is refilled
    }
}

// ---------------- slot LN + q projection (+ zero denom) ----------------
__global__ void __launch_bounds__(256)
slot_q(int it, const float* __restrict__ cond,
       const float* __restrict__ lw, const float* __restrict__ lb) {
    const float* src = (it == 0) ? cond : (it == 1 ? g_slotsA : g_slotsB);
    int row = blockIdx.x, t = threadIdx.x;
    float v = src[row*256 + t];
    float s = v, ss = v*v;
#pragma unroll
    for (int o = 16; o; o >>= 1) {
        s  += __shfl_xor_sync(0xffffffffu, s,  o);
        ss += __shfl_xor_sync(0xffffffffu, ss, o);
    }
    __shared__ float ps[8], pss[8];
    __shared__ float smu, srs;
    __shared__ float sn[256];
    if ((t & 31) == 0) { ps[t>>5] = s; pss[t>>5] = ss; }
    __syncthreads();
    if (t == 0) {
        float S = 0.f, SS = 0.f;
#pragma unroll
        for (int i = 0; i < 8; i++) { S += ps[i]; SS += pss[i]; }
        float mu = S * (1.f/256.f);
        smu = mu;
        srs = rsqrtf(SS * (1.f/256.f) - mu*mu + LN_EPS);
    }
    if (t < 4) g_denom[row*4 + t] = 0.f;
    __syncthreads();
    sn[t] = (v - smu)*srs*lw[t] + lb[t];
    __syncthreads();
    float acc = 0.f;
#pragma unroll 4
    for (int d = 0; d < 256; d++) acc += sn[d] * g_WqT[d*256 + t];
    g_q[row*256 + t] = acc * SCALE;
}

// ---------------- dots + 32-way softmax + denom + outputs ----------------
__global__ void __launch_bounds__(256)
dots_softmax(float* __restrict__ out_stack, float* __restrict__ out_last) {
    int b = blockIdx.y, jt = blockIdx.x;
    int j0 = jt * 32;
    int tid = threadIdx.x, w = tid >> 5, lane = tid & 31;
    int hl = lane >> 3, dsub = lane & 7;

    __shared__ float qs[2048];
    __shared__ float attn_s[32][33];
    __shared__ float stk_s[8][33];
    __shared__ float den_s[32];

    if (tid < 16) g_upd[(b*128 + jt)*16 + tid] = 0.f;
    if (tid < 32) den_s[tid] = 0.f;
#pragma unroll
    for (int r = 0; r < 8; r++) qs[r*256 + tid] = g_q[b*2048 + r*256 + tid];
    __syncthreads();

    unsigned long long qp[8][4];
#pragma unroll
    for (int i = 0; i < 8; i++)
#pragma unroll
        for (int p = 0; p < 4; p++) {
            int base = i*256 + hl*64 + dsub*8 + p*2;
            PK2(qp[i][p], qs[base], qs[base+1]);
        }

    float dsum[8];
#pragma unroll
    for (int i = 0; i < 8; i++) dsum[i] = 0.f;

    for (int jj = 0; jj < 4; jj++) {
        int j = j0 + w*4 + jj;
        const float4* krow = (const float4*)&g_kv[(size_t)(b*NN + j)*512];
        float4 k0 = krow[lane*2], k1 = krow[lane*2 + 1];
        unsigned long long kp[4];
        PK2(kp[0], k0.x, k0.y); PK2(kp[1], k0.z, k0.w);
        PK2(kp[2], k1.x, k1.y); PK2(kp[3], k1.z, k1.w);

        float part[8];
#pragma unroll
        for (int i = 0; i < 8; i++) {
            unsigned long long a = 0ull;
            FMA2(a, qp[i][0], kp[0], a);
            FMA2(a, qp[i][1], kp[1], a);
            FMA2(a, qp[i][2], kp[2], a);
            FMA2(a, qp[i][3], kp[3], a);
            float x0, x1; UPK2(x0, x1, a);
            part[i] = x0 + x1;
        }
#pragma unroll
        for (int i = 0; i < 8; i++) {
            part[i] += __shfl_xor_sync(0xffffffffu, part[i], 1);
            part[i] += __shfl_xor_sync(0xffffffffu, part[i], 2);
            part[i] += __shfl_xor_sync(0xffffffffu, part[i], 4);
        }
        float mx = part[0];
#pragma unroll
        for (int i = 1; i < 8; i++) mx = fmaxf(mx, part[i]);
        mx = fmaxf(mx, __shfl_xor_sync(0xffffffffu, mx, 8));
        mx = fmaxf(mx, __shfl_xor_sync(0xffffffffu, mx, 16));
        float e[8], ssum = 0.f;
#pragma unroll
        for (int i = 0; i < 8; i++) { e[i] = __expf(part[i] - mx); ssum += e[i]; }
        ssum += __shfl_xor_sync(0xffffffffu, ssum, 8);
        ssum += __shfl_xor_sync(0xffffffffu, ssum, 16);
        float inv = 1.f / ssum;
#pragma unroll
        for (int i = 0; i < 8; i++) e[i] *= inv;
        float ms[8];
#pragma unroll
        for (int i = 0; i < 8; i++) {
            float tv = e[i];
            tv += __shfl_xor_sync(0xffffffffu, tv, 8);
            tv += __shfl_xor_sync(0xffffffffu, tv, 16);
            ms[i] = tv;
        }
        if (dsub == 0) {
            int jloc = w*4 + jj;
#pragma unroll
            for (int i = 0; i < 8; i++) { attn_s[i*4 + hl][jloc] = e[i]; dsum[i] += e[i]; }
            if (hl == 0) {
#pragma unroll
                for (int i = 0; i < 8; i++) stk_s[i][jloc] = ms[i] * 0.25f;
            }
        }
    }

    if (dsub == 0) {
#pragma unroll
        for (int i = 0; i < 8; i++) atomicAdd(&den_s[i*4 + hl], dsum[i]);
    }
    __syncthreads();
    if (tid < 32) atomicAdd(&g_denom[b*32 + tid], den_s[tid]);

#pragma unroll
    for (int r = 0; r < 4; r++) {
        int idx = r*256 + tid; int ih = idx >> 5, jc = idx & 31;
        g_attn[(size_t)(b*32 + ih)*NN + j0 + jc] = attn_s[ih][jc];
    }
    {
        int i = tid >> 5, jc = tid & 31;
        float v = stk_s[i][jc];
        size_t o = (size_t)(b*8 + i)*NN + j0 + jc;
        out_stack[o] = v;
        if (out_last) out_last[o] = v;
    }
}

// ---------------- updates = (attn/denom) @ v ----------------
__global__ void __launch_bounds__(256)
upd_kernel() {
    int chunk = blockIdx.x, h = blockIdx.y, b = blockIdx.z;
    int tid = threadIdx.x;
    int d = tid & 63, js = tid >> 6;
    __shared__ float at_s[8][128];
    __shared__ float dinv[8];
    if (tid < 8) dinv[tid] = 1.f / (g_denom[b*32 + tid*4 + h] + SUM_EPS);
    float acc[8];
#pragma unroll
    for (int i = 0; i < 8; i++) acc[i] = 0.f;
    int j0 = chunk * 1024;
    for (int sc = 0; sc < 8; sc++) {
        __syncthreads();
#pragma unroll
        for (int r = 0; r < 4; r++) {
            int idx = r*256 + tid; int i = idx >> 7, jc = idx & 127;
            at_s[i][jc] = g_attn[(size_t)(b*32 + i*4 + h)*NN + j0 + sc*128 + jc];
        }
        __syncthreads();
#pragma unroll 4
        for (int jj = 0; jj < 32; jj++) {
            int jl = jj*4 + js;
            float vv = g_kv[(size_t)(b*NN + j0 + sc*128 + jl)*512 + 256 + h*64 + d];
#pragma unroll
            for (int i = 0; i < 8; i++) acc[i] += vv * at_s[i][jl];
        }
    }
#pragma unroll
    for (int i = 0; i < 8; i++)
        atomicAdd(&g_upd[(b*8 + i)*256 + h*64 + d], acc[i] * dinv[i]);
}

// ---------------- GRU cell (4 rows per block for weight reuse) ----------------
__global__ void __launch_bounds__(256)
gru_kernel(int it, const float* __restrict__ cond, float* __restrict__ out_slots,
           const float* __restrict__ bih, const float* __restrict__ bhh) {
    const float* hsrc = (it == 0) ? cond : (it == 1 ? g_slotsA : g_slotsB);
    float* dst = (it == 0) ? g_slotsA : (it == 1 ? g_slotsB : out_slots);
    int t = threadIdx.x;
    __shared__ float u_s[4][256], h_s[4][256];
#pragma unroll
    for (int r = 0; r < 4; r++) {
        int row = blockIdx.x*4 + r;
        u_s[r][t] = g_upd[row*256 + t];
        h_s[r][t] = hsrc[row*256 + t];
    }
    __syncthreads();
    float axr[4] = {0,0,0,0}, axz[4] = {0,0,0,0}, axn[4] = {0,0,0,0};
    float ahr[4] = {0,0,0,0}, ahz[4] = {0,0,0,0}, ahn[4] = {0,0,0,0};
#pragma unroll 2
    for (int dd = 0; dd < 256; dd++) {
        float wr = g_WihT[dd*768 + t],       wz = g_WihT[dd*768 + 256 + t];
        float wn = g_WihT[dd*768 + 512 + t];
        float vr = g_WhhT[dd*768 + t],       vz = g_WhhT[dd*768 + 256 + t];
        float vn = g_WhhT[dd*768 + 512 + t];
#pragma unroll
        for (int r = 0; r < 4; r++) {
            float u = u_s[r][dd], hh = h_s[r][dd];
            axr[r] += u*wr;  axz[r] += u*wz;  axn[r] += u*wn;
            ahr[r] += hh*vr; ahz[r] += hh*vz; ahn[r] += hh*vn;
        }
    }
    float br = bih[t], bz = bih[256 + t], bn = bih[512 + t];
    float cr = bhh[t], cz = bhh[256 + t], cn = bhh[512 + t];
#pragma unroll
    for (int r = 0; r < 4; r++) {
        float rg = 1.f / (1.f + __expf(-(axr[r] + ahr[r] + br + cr)));
        float zg = 1.f / (1.f + __expf(-(axz[r] + ahz[r] + bz + cz)));
        float ng = tanhf(axn[r] + bn + rg*(ahn[r] + cn));
        int row = blockIdx.x*4 + r;
        dst[row*256 + t] = (1.f - zg)*ng + zg*h_s[r][t];
    }
}

// ---------------- launch ----------------
extern "C" void kernel_launch(void* const* d_in, const int* in_sizes, int n_in,
                              void* d_out, int out_size) {
    (void)in_sizes; (void)n_in; (void)out_size;
    const float* x    = (const float*)d_in[0];
    const float* cond = (const float*)d_in[1];
    const float* lniw = (const float*)d_in[2];
    const float* lnib = (const float*)d_in[3];
    const float* lnsw = (const float*)d_in[4];
    const float* lnsb = (const float*)d_in[5];
    const float* Wq   = (const float*)d_in[6];
    const float* Wk   = (const float*)d_in[7];
    const float* Wv   = (const float*)d_in[8];
    const float* wih  = (const float*)d_in[9];
    const float* whh  = (const float*)d_in[10];
    const float* bih  = (const float*)d_in[11];
    const float* bhh  = (const float*)d_in[12];

    float* out       = (float*)d_out;
    float* out_slots = out;                       // [64,8,256]
    float* out_last  = out + 131072;              // [64,8,4096]
    float* out_stack = out + 131072 + 2097152;    // [3,64,8,4096]

    cudaFuncSetAttribute(kv_hmma, cudaFuncAttributeMaxDynamicSharedMemorySize, KV_SMEM);

    prep_w<<<768, 256>>>(Wq, wih, whh);
    prep_b<<<512, 256>>>(Wk, Wv);
    ln_stats<<<ROWS/8, 256>>>(x);
    kv_hmma<<<2048, 256, KV_SMEM>>>(x, lniw, lnib);

    for (int it = 0; it < 3; it++) {
        slot_q<<<512, 256>>>(it, cond, lnsw, lnsb);
        dots_softmax<<<dim3(128, 64), 256>>>(out_stack + (size_t)it*2097152,
                                             (it == 2) ? out_last : (float*)0);
        upd_kernel<<<dim3(4, 4, 64), 256>>>();
        gru_kernel<<<128, 256>>>(it, cond, out_slots, bih, bhh);
    }
}

// round 12
// speedup vs baseline: 1.6333x; 1.1400x over previous
#include <cuda_runtime.h>
#include <cuda_bf16.h>
#include <math.h>

#define NB 64
#define NN 4096
#define ROWS (NB*NN)          // 262144
#define SCALE 0.125f
#define LN_EPS 1e-5f
#define SUM_EPS 1e-8f

// ---------------- device scratch (no allocations allowed) ----------------
__device__ float g_kv[(size_t)ROWS*512];   // [row][0:256]=k, [256:512]=v
__device__ float g_WqT[256*256];
__device__ float g_WihT[256*768];
__device__ float g_WhhT[256*768];
__device__ float g_mu[ROWS];
__device__ float g_rs[ROWS];
__device__ float g_q[512*256];             // [(b*8+i)][h*64+d], pre-scaled
__device__ float g_attn[(size_t)NB*32*NN]; // [b][ih][j] softmaxed (pre-renorm)
__device__ float g_denom[NB*32];
__device__ float g_upd[512*256];
__device__ float g_slotsA[512*256];
__device__ float g_slotsB[512*256];
// plain row-major bf16 hi/lo images of Wk|Wv: [o in 0..511][k in 0..255]
__device__ __align__(16) unsigned short g_Bhi_img[512*256];
__device__ __align__(16) unsigned short g_Blo_img[512*256];

// ---------------- f32x2 packed-FMA helpers (Blackwell) ----------------
#define PK2(d,x,y)   asm("mov.b64 %0, {%1,%2};"          : "=l"(d) : "f"(x), "f"(y))
#define UPK2(x,y,d)  asm("mov.b64 {%0,%1}, %2;"          : "=f"(x), "=f"(y) : "l"(d))
#define FMA2(d,a,b,c) asm("fma.rn.f32x2 %0, %1, %2, %3;" : "=l"(d) : "l"(a), "l"(b), "l"(c))

// ---------------- baseline-PTX tensor-core helpers (sm_80+) ----------------
__device__ __forceinline__ unsigned smem_u32(const void* p) {
    unsigned a;
    asm("{ .reg .u64 t; cvta.to.shared.u64 t, %1; cvt.u32.u64 %0, t; }" : "=r"(a) : "l"(p));
    return a;
}
#define LDSM4(r, a) \
    asm volatile("ldmatrix.sync.aligned.m8n8.x4.shared.b16 {%0,%1,%2,%3}, [%4];" \
        : "=r"((r)[0]), "=r"((r)[1]), "=r"((r)[2]), "=r"((r)[3]) : "r"(a))
#define MMA16816(d, a, b) \
    asm volatile("mma.sync.aligned.m16n8k16.row.col.f32.bf16.bf16.f32 " \
        "{%0,%1,%2,%3},{%4,%5,%6,%7},{%8,%9},{%0,%1,%2,%3};" \
        : "+f"((d)[0]), "+f"((d)[1]), "+f"((d)[2]), "+f"((d)[3]) \
        : "r"((a)[0]), "r"((a)[1]), "r"((a)[2]), "r"((a)[3]), "r"((b)[0]), "r"((b)[1]))
#define CP_ASYNC16(dst, src) \
    asm volatile("cp.async.cg.shared.global [%0], [%1], 16;" :: "r"(dst), "l"(src))
#define CP_COMMIT() asm volatile("cp.async.commit_group;" ::: "memory")
#define CP_WAIT1()  asm volatile("cp.async.wait_group 1;"  ::: "memory")
#define CP_WAIT0()  asm volatile("cp.async.wait_group 0;"  ::: "memory")

// ---------------- prep: transpose weights (Wq / GRU) ----------------
__global__ void prep_w(const float* __restrict__ Wq, const float* __restrict__ wih,
                       const float* __restrict__ whh) {
    int idx = blockIdx.x*256 + threadIdx.x;          // < 196608
    if (idx < 256*256) {
        int d = idx >> 8, o = idx & 255;
        g_WqT[idx] = Wq[o*256 + d];
    }
    {
        int d = idx / 768, o = idx - d*768;
        g_WihT[idx] = wih[o*256 + d];
        g_WhhT[idx] = whh[o*256 + d];
    }
}

// ---------------- prep: bf16 hi/lo split of Wk|Wv (plain row-major) --------
__global__ void prep_b(const float* __restrict__ Wk, const float* __restrict__ Wv) {
    int o = blockIdx.x, k = threadIdx.x;
    float w = (o < 256) ? Wk[o*256 + k] : Wv[(o-256)*256 + k];
    __nv_bfloat16 hi = __float2bfloat16(w);
    __nv_bfloat16 lo = __float2bfloat16(w - __bfloat162float(hi));
    g_Bhi_img[o*256 + k] = __bfloat16_as_ushort(hi);
    g_Blo_img[o*256 + k] = __bfloat16_as_ushort(lo);
}

// ---------------- LayerNorm stats (warp per row) ----------------
__global__ void ln_stats(const float* __restrict__ x) {
    int row  = blockIdx.x*8 + (threadIdx.x >> 5);
    int lane = threadIdx.x & 31;
    const float4* xr = (const float4*)(x + (size_t)row*256);
    float s = 0.f, ss = 0.f;
#pragma unroll
    for (int i = 0; i < 2; i++) {
        float4 v = xr[lane + 32*i];
        s  += v.x + v.y + v.z + v.w;
        ss += v.x*v.x + v.y*v.y + v.z*v.z + v.w*v.w;
    }
#pragma unroll
    for (int o = 16; o; o >>= 1) {
        s  += __shfl_xor_sync(0xffffffffu, s,  o);
        ss += __shfl_xor_sync(0xffffffffu, ss, o);
    }
    if (lane == 0) {
        float mu  = s * (1.f/256.f);
        float var = ss * (1.f/256.f) - mu*mu;
        g_mu[row] = mu;
        g_rs[row] = rsqrtf(var + LN_EPS);
    }
}

// ---------------- HMMA K/V GEMM fragments ----------------
struct Frags {
    unsigned a0[4], a1[4], l0[4], l1[4];   // A hi (2 m-tiles), A lo (2 m-tiles)
    unsigned bh[8], bl[8];                 // B hi/lo (2 n-sub-tiles each)
};

__device__ __forceinline__ void load_frags(
    Frags& f, int ks, int half, unsigned buf,
    unsigned aBase0, unsigned aBase1, unsigned klA, unsigned xA,
    unsigned nB0row, unsigned nB1row, unsigned kbB, unsigned xB)
{
    unsigned kgA = (unsigned)(half*8 + ks)*2u + klA;
    unsigned aoff = ((kgA ^ xA) << 4);
    LDSM4(f.a0, aBase0 + aoff);
    LDSM4(f.a1, aBase1 + aoff);
    LDSM4(f.l0, aBase0 + 65536u + aoff);
    LDSM4(f.l1, aBase1 + 65536u + aoff);
    unsigned kgB = (unsigned)ks*2u + kbB;
    unsigned b0off = nB0row + ((kgB ^ xB) << 4);
    unsigned b1off = nB1row + ((kgB ^ xB) << 4);
    LDSM4(&f.bh[0], buf + b0off);
    LDSM4(&f.bh[4], buf + b1off);
    LDSM4(&f.bl[0], buf + 16384u + b0off);
    LDSM4(&f.bl[4], buf + 16384u + b1off);
}

__device__ __forceinline__ void do_mmas(float acc[2][4][4], const Frags& f) {
#pragma unroll
    for (int j = 0; j < 4; j++) {
        MMA16816(acc[0][j], f.a0, &f.bh[j*2]);
        MMA16816(acc[1][j], f.a1, &f.bh[j*2]);
    }
#pragma unroll
    for (int j = 0; j < 4; j++) {
        MMA16816(acc[0][j], f.a0, &f.bl[j*2]);
        MMA16816(acc[1][j], f.a1, &f.bl[j*2]);
    }
#pragma unroll
    for (int j = 0; j < 4; j++) {
        MMA16816(acc[0][j], f.l0, &f.bh[j*2]);
        MMA16816(acc[1][j], f.l1, &f.bh[j*2]);
    }
}

// ---------------- HMMA K/V GEMM: [262144,256] @ [256,512], 3x bf16-split ----
// CTA = 128 rows x 512 outputs. A (hi+lo) resident in smem; B streamed in 16
// chunks (nb 0..7 x k-half 0..1) of 32KB each via cp.async double buffering.
// Register double-buffering of ldmatrix fragments across k-steps.
#define KV_SMEM 196608

__global__ void __launch_bounds__(256, 1)
kv_hmma(const float* __restrict__ x, const float* __restrict__ lw,
        const float* __restrict__ lb) {
    extern __shared__ char smem[];
    __shared__ float smu[128], srs[128];

    const unsigned sb  = smem_u32(smem);
    const unsigned sbB = sb + 131072u;
    int tid = threadIdx.x, wid = tid >> 5, lane = tid & 31;
    int m0 = blockIdx.x * 128;

    if (tid < 128) { smu[tid] = g_mu[m0 + tid]; srs[tid] = g_rs[m0 + tid]; }

    // ---- prefetch B chunk 0 into buffer 0 ----
    {
#pragma unroll
        for (int it = 0; it < 8; it++) {
            int u = tid + it*256;
            int split = u >> 10, rem = u & 1023;
            int o = rem >> 4, g = rem & 15;
            const char* img = split ? (const char*)g_Blo_img : (const char*)g_Bhi_img;
            const char* src = img + (size_t)o*512 + g*16;    // nb=0, half=0
            unsigned dst = sbB + split*16384 + o*256 + ((unsigned)(g ^ (o & 7)) << 4);
            CP_ASYNC16(dst, src);
        }
        CP_COMMIT();
    }
    __syncthreads();   // smu/srs visible

    // ---- load A with fused LN, split into bf16 hi/lo, swizzled ----
    {
        int cpair = tid & 127;            // column pair index
        int c2 = cpair * 2;
        int rbase = (tid >> 7) * 64;
        float w0 = lw[c2], w1 = lw[c2+1], bb0 = lb[c2], bb1 = lb[c2+1];
        unsigned gA = (unsigned)(cpair >> 2);
        unsigned boff = (unsigned)(cpair & 3) * 4u;
#pragma unroll 4
        for (int r = 0; r < 64; r++) {
            int row = rbase + r;
            float2 xv = *(const float2*)&x[(size_t)(m0 + row)*256 + c2];
            float mu = smu[row], rs = srs[row];
            float v0 = (xv.x - mu)*rs*w0 + bb0;
            float v1 = (xv.y - mu)*rs*w1 + bb1;
            __nv_bfloat16 h0 = __float2bfloat16(v0);
            __nv_bfloat16 h1 = __float2bfloat16(v1);
            __nv_bfloat16 l0 = __float2bfloat16(v0 - __bfloat162float(h0));
            __nv_bfloat16 l1 = __float2bfloat16(v1 - __bfloat162float(h1));
            unsigned hp = (unsigned)__bfloat16_as_ushort(h0) |
                          ((unsigned)__bfloat16_as_ushort(h1) << 16);
            unsigned lp = (unsigned)__bfloat16_as_ushort(l0) |
                          ((unsigned)__bfloat16_as_ushort(l1) << 16);
            unsigned phys = (unsigned)row*512u + ((gA ^ (unsigned)(row & 7)) << 4) + boff;
            *(unsigned*)(smem + phys)          = hp;
            *(unsigned*)(smem + 65536 + phys)  = lp;
        }
    }

    // ---- warp tiling: 4 M-warps x 2 N-warps, warp tile m32 x n32 ----
    int mw = wid >> 1, nw = wid & 1;
    int rA0 = mw*32 + (lane & 15);                       // ldmatrix A lane row, mtile0
    int rA1 = rA0 + 16;
    unsigned klA = (unsigned)(lane >> 4);                // A k-granule low bit
    unsigned xA = (unsigned)(rA0 & 7);                   // same for rA1
    unsigned aBase0 = sb + (unsigned)rA0*512u;
    unsigned aBase1 = sb + (unsigned)rA1*512u;

    int nB0 = nw*32 + (lane & 7) + ((lane >> 4) & 1)*8;  // ldmatrix B lane row (n index)
    int nB1 = nB0 + 16;
    unsigned nB0row = (unsigned)nB0*256u;
    unsigned nB1row = (unsigned)nB1*256u;
    unsigned kbB = (unsigned)((lane >> 3) & 1);          // B k-granule low bit
    unsigned xB = (unsigned)(nB0 & 7);

    float acc[2][4][4];
#pragma unroll
    for (int i = 0; i < 2; i++)
#pragma unroll
        for (int j = 0; j < 4; j++)
#pragma unroll
            for (int q = 0; q < 4; q++) acc[i][j][q] = 0.f;

    for (int c = 0; c < 16; c++) {
        // prefetch chunk c+1 into the other buffer
        if (c + 1 < 16) {
            int nbn = (c + 1) >> 1, halfn = (c + 1) & 1;
            unsigned bufn = sbB + (unsigned)((c + 1) & 1)*32768u;
#pragma unroll
            for (int it = 0; it < 8; it++) {
                int u = tid + it*256;
                int split = u >> 10, rem = u & 1023;
                int o = rem >> 4, g = rem & 15;
                const char* img = split ? (const char*)g_Blo_img : (const char*)g_Bhi_img;
                const char* src = img + (size_t)(nbn*64 + o)*512 + halfn*256 + g*16;
                unsigned dst = bufn + split*16384 + o*256 + ((unsigned)(g ^ (o & 7)) << 4);
                CP_ASYNC16(dst, src);
            }
            CP_COMMIT();
            CP_WAIT1();
        } else {
            CP_WAIT0();
        }
        __syncthreads();   // chunk c ready in buf c&1; also A ready on first iter

        unsigned buf = sbB + (unsigned)(c & 1)*32768u;
        int half = c & 1;

        // register double-buffered k-step pipeline
        Frags fr0, fr1;
        load_frags(fr0, 0, half, buf, aBase0, aBase1, klA, xA,
                   nB0row, nB1row, kbB, xB);
#pragma unroll
        for (int ks = 0; ks < 8; ks++) {
            Frags& cur = (ks & 1) ? fr1 : fr0;
            Frags& nxt = (ks & 1) ? fr0 : fr1;
            if (ks < 7)
                load_frags(nxt, ks + 1, half, buf, aBase0, aBase1, klA, xA,
                           nB0row, nB1row, kbB, xB);
            do_mmas(acc, cur);
        }

        if (c & 1) {
            // n-block (c>>1) complete: write out and reset accumulators
            int nbidx = c >> 1;
#pragma unroll
            for (int i = 0; i < 2; i++) {
#pragma unroll
                for (int j = 0; j < 4; j++) {
                    int row = m0 + mw*32 + i*16 + (lane >> 2);
                    int col = nbidx*64 + nw*32 + j*8 + (lane & 3)*2;
                    float2 o0 = {acc[i][j][0], acc[i][j][1]};
                    float2 o1 = {acc[i][j][2], acc[i][j][3]};
                    *(float2*)&g_kv[(size_t)row*512 + col]       = o0;
                    *(float2*)&g_kv[(size_t)(row + 8)*512 + col] = o1;
                    acc[i][j][0] = acc[i][j][1] = acc[i][j][2] = acc[i][j][3] = 0.f;
                }
            }
        }
        __syncthreads();   // everyone done with buf c&1 before it is refilled
    }
}

// ---------------- slot LN + q projection (+ zero denom) ----------------
// One block per batch b: 8 warps = 8 slot rows; WqT tiled through smem.
__global__ void __launch_bounds__(256)
slot_q(int it, const float* __restrict__ cond,
       const float* __restrict__ lw, const float* __restrict__ lb) {
    const float* src = (it == 0) ? cond : (it == 1 ? g_slotsA : g_slotsB);
    int b = blockIdx.x, t = threadIdx.x, wid = t >> 5, lane = t & 31;

    __shared__ float sn[8][256];
    __shared__ float wt[32][256];

    // warp wid handles slot row wid: LN via shfl
    const float4* row = (const float4*)(src + (size_t)(b*8 + wid)*256);
    float4 v0 = row[lane], v1 = row[lane + 32];
    float s  = v0.x + v0.y + v0.z + v0.w + v1.x + v1.y + v1.z + v1.w;
    float ss = v0.x*v0.x + v0.y*v0.y + v0.z*v0.z + v0.w*v0.w
             + v1.x*v1.x + v1.y*v1.y + v1.z*v1.z + v1.w*v1.w;
#pragma unroll
    for (int o = 16; o; o >>= 1) {
        s  += __shfl_xor_sync(0xffffffffu, s,  o);
        ss += __shfl_xor_sync(0xffffffffu, ss, o);
    }
    float mu = s * (1.f/256.f);
    float rs = rsqrtf(ss * (1.f/256.f) - mu*mu + LN_EPS);
#pragma unroll
    for (int i = 0; i < 2; i++) {
        float4 xv = i ? v1 : v0;
        int c = (lane + 32*i) * 4;
        float4 w4 = *(const float4*)&lw[c];
        float4 b4 = *(const float4*)&lb[c];
        sn[wid][c+0] = (xv.x - mu)*rs*w4.x + b4.x;
        sn[wid][c+1] = (xv.y - mu)*rs*w4.y + b4.y;
        sn[wid][c+2] = (xv.z - mu)*rs*w4.z + b4.z;
        sn[wid][c+3] = (xv.w - mu)*rs*w4.w + b4.w;
    }
    if (t < 32) g_denom[b*32 + t] = 0.f;
    __syncthreads();

    float acc[8] = {0,0,0,0,0,0,0,0};
    for (int d0 = 0; d0 < 256; d0 += 32) {
        // cooperative load of WqT[d0..d0+32)[0..256) : 32KB
        __syncthreads();
#pragma unroll
        for (int i = 0; i < 8; i++) {
            int u = t + i*256;                     // < 2048 float4
            int dd = u >> 6, g = u & 63;
            *(float4*)&wt[dd][g*4] = *(const float4*)&g_WqT[(d0 + dd)*256 + g*4];
        }
        __syncthreads();
#pragma unroll 4
        for (int dd = 0; dd < 32; dd++) {
            float w = wt[dd][t];
#pragma unroll
            for (int r = 0; r < 8; r++) acc[r] += sn[r][d0 + dd] * w;
        }
    }
#pragma unroll
    for (int r = 0; r < 8; r++) g_q[(size_t)(b*8 + r)*256 + t] = acc[r] * SCALE;
}

// ---------------- dots + 32-way softmax + denom + outputs ----------------
__global__ void __launch_bounds__(256)
dots_softmax(float* __restrict__ out_stack, float* __restrict__ out_last) {
    int b = blockIdx.y, jt = blockIdx.x;
    int j0 = jt * 32;
    int tid = threadIdx.x, w = tid >> 5, lane = tid & 31;
    int hl = lane >> 3, dsub = lane & 7;

    __shared__ float qs[2048];
    __shared__ float attn_s[32][33];
    __shared__ float stk_s[8][33];
    __shared__ float den_s[32];

    if (tid < 16) g_upd[(b*128 + jt)*16 + tid] = 0.f;
    if (tid < 32) den_s[tid] = 0.f;
#pragma unroll
    for (int r = 0; r < 8; r++) qs[r*256 + tid] = g_q[b*2048 + r*256 + tid];
    __syncthreads();

    unsigned long long qp[8][4];
#pragma unroll
    for (int i = 0; i < 8; i++)
#pragma unroll
        for (int p = 0; p < 4; p++) {
            int base = i*256 + hl*64 + dsub*8 + p*2;
            PK2(qp[i][p], qs[base], qs[base+1]);
        }

    float dsum[8];
#pragma unroll
    for (int i = 0; i < 8; i++) dsum[i] = 0.f;

    // hoist all 4 k-row loads for MLP
    float4 kr0[4], kr1[4];
#pragma unroll
    for (int jj = 0; jj < 4; jj++) {
        int j = j0 + w*4 + jj;
        const float4* krow = (const float4*)&g_kv[(size_t)(b*NN + j)*512];
        kr0[jj] = krow[lane*2];
        kr1[jj] = krow[lane*2 + 1];
    }

#pragma unroll
    for (int jj = 0; jj < 4; jj++) {
        unsigned long long kp[4];
        PK2(kp[0], kr0[jj].x, kr0[jj].y); PK2(kp[1], kr0[jj].z, kr0[jj].w);
        PK2(kp[2], kr1[jj].x, kr1[jj].y); PK2(kp[3], kr1[jj].z, kr1[jj].w);

        float part[8];
#pragma unroll
        for (int i = 0; i < 8; i++) {
            unsigned long long a = 0ull;
            FMA2(a, qp[i][0], kp[0], a);
            FMA2(a, qp[i][1], kp[1], a);
            FMA2(a, qp[i][2], kp[2], a);
            FMA2(a, qp[i][3], kp[3], a);
            float x0, x1; UPK2(x0, x1, a);
            part[i] = x0 + x1;
        }
#pragma unroll
        for (int i = 0; i < 8; i++) {
            part[i] += __shfl_xor_sync(0xffffffffu, part[i], 1);
            part[i] += __shfl_xor_sync(0xffffffffu, part[i], 2);
            part[i] += __shfl_xor_sync(0xffffffffu, part[i], 4);
        }
        float mx = part[0];
#pragma unroll
        for (int i = 1; i < 8; i++) mx = fmaxf(mx, part[i]);
        mx = fmaxf(mx, __shfl_xor_sync(0xffffffffu, mx, 8));
        mx = fmaxf(mx, __shfl_xor_sync(0xffffffffu, mx, 16));
        float e[8], ssum = 0.f;
#pragma unroll
        for (int i = 0; i < 8; i++) { e[i] = __expf(part[i] - mx); ssum += e[i]; }
        ssum += __shfl_xor_sync(0xffffffffu, ssum, 8);
        ssum += __shfl_xor_sync(0xffffffffu, ssum, 16);
        float inv = 1.f / ssum;
#pragma unroll
        for (int i = 0; i < 8; i++) e[i] *= inv;
        float ms[8];
#pragma unroll
        for (int i = 0; i < 8; i++) {
            float tv = e[i];
            tv += __shfl_xor_sync(0xffffffffu, tv, 8);
            tv += __shfl_xor_sync(0xffffffffu, tv, 16);
            ms[i] = tv;
        }
        if (dsub == 0) {
            int jloc = w*4 + jj;
#pragma unroll
            for (int i = 0; i < 8; i++) { attn_s[i*4 + hl][jloc] = e[i]; dsum[i] += e[i]; }
            if (hl == 0) {
#pragma unroll
                for (int i = 0; i < 8; i++) stk_s[i][jloc] = ms[i] * 0.25f;
            }
        }
    }

    if (dsub == 0) {
#pragma unroll
        for (int i = 0; i < 8; i++) atomicAdd(&den_s[i*4 + hl], dsum[i]);
    }
    __syncthreads();
    if (tid < 32) atomicAdd(&g_denom[b*32 + tid], den_s[tid]);

#pragma unroll
    for (int r = 0; r < 4; r++) {
        int idx = r*256 + tid; int ih = idx >> 5, jc = idx & 31;
        g_attn[(size_t)(b*32 + ih)*NN + j0 + jc] = attn_s[ih][jc];
    }
    {
        int i = tid >> 5, jc = tid & 31;
        float v = stk_s[i][jc];
        size_t o = (size_t)(b*8 + i)*NN + j0 + jc;
        out_stack[o] = v;
        if (out_last) out_last[o] = v;
    }
}

// ---------------- updates = (attn/denom) @ v ----------------
__global__ void __launch_bounds__(256)
upd_kernel() {
    int chunk = blockIdx.x, h = blockIdx.y, b = blockIdx.z;
    int tid = threadIdx.x;
    int d = tid & 63, js = tid >> 6;
    __shared__ float at_s[8][128];
    __shared__ float dinv[8];
    if (tid < 8) dinv[tid] = 1.f / (g_denom[b*32 + tid*4 + h] + SUM_EPS);
    float acc[8];
#pragma unroll
    for (int i = 0; i < 8; i++) acc[i] = 0.f;
    int j0 = chunk * 1024;
    for (int sc = 0; sc < 8; sc++) {
        __syncthreads();
#pragma unroll
        for (int r = 0; r < 4; r++) {
            int idx = r*256 + tid; int i = idx >> 7, jc = idx & 127;
            at_s[i][jc] = g_attn[(size_t)(b*32 + i*4 + h)*NN + j0 + sc*128 + jc];
        }
        __syncthreads();
#pragma unroll 8
        for (int jj = 0; jj < 32; jj++) {
            int jl = jj*4 + js;
            float vv = g_kv[(size_t)(b*NN + j0 + sc*128 + jl)*512 + 256 + h*64 + d];
#pragma unroll
            for (int i = 0; i < 8; i++) acc[i] += vv * at_s[i][jl];
        }
    }
#pragma unroll
    for (int i = 0; i < 8; i++)
        atomicAdd(&g_upd[(b*8 + i)*256 + h*64 + d], acc[i] * dinv[i]);
}

// ---------------- GRU cell (4 rows per block for weight reuse) ----------------
__global__ void __launch_bounds__(256)
gru_kernel(int it, const float* __restrict__ cond, float* __restrict__ out_slots,
           const float* __restrict__ bih, const float* __restrict__ bhh) {
    const float* hsrc = (it == 0) ? cond : (it == 1 ? g_slotsA : g_slotsB);
    float* dst = (it == 0) ? g_slotsA : (it == 1 ? g_slotsB : out_slots);
    int t = threadIdx.x;
    __shared__ float u_s[4][256], h_s[4][256];
#pragma unroll
    for (int r = 0; r < 4; r++) {
        int row = blockIdx.x*4 + r;
        u_s[r][t] = g_upd[row*256 + t];
        h_s[r][t] = hsrc[row*256 + t];
    }
    __syncthreads();
    float axr[4] = {0,0,0,0}, axz[4] = {0,0,0,0}, axn[4] = {0,0,0,0};
    float ahr[4] = {0,0,0,0}, ahz[4] = {0,0,0,0}, ahn[4] = {0,0,0,0};
#pragma unroll 2
    for (int dd = 0; dd < 256; dd++) {
        float wr = g_WihT[dd*768 + t],       wz = g_WihT[dd*768 + 256 + t];
        float wn = g_WihT[dd*768 + 512 + t];
        float vr = g_WhhT[dd*768 + t],       vz = g_WhhT[dd*768 + 256 + t];
        float vn = g_WhhT[dd*768 + 512 + t];
#pragma unroll
        for (int r = 0; r < 4; r++) {
            float u = u_s[r][dd], hh = h_s[r][dd];
            axr[r] += u*wr;  axz[r] += u*wz;  axn[r] += u*wn;
            ahr[r] += hh*vr; ahz[r] += hh*vz; ahn[r] += hh*vn;
        }
    }
    float br = bih[t], bz = bih[256 + t], bn = bih[512 + t];
    float cr = bhh[t], cz = bhh[256 + t], cn = bhh[512 + t];
#pragma unroll
    for (int r = 0; r < 4; r++) {
        float rg = 1.f / (1.f + __expf(-(axr[r] + ahr[r] + br + cr)));
        float zg = 1.f / (1.f + __expf(-(axz[r] + ahz[r] + bz + cz)));
        float ng = tanhf(axn[r] + bn + rg*(ahn[r] + cn));
        int row = blockIdx.x*4 + r;
        dst[row*256 + t] = (1.f - zg)*ng + zg*h_s[r][t];
    }
}

// ---------------- launch ----------------
extern "C" void kernel_launch(void* const* d_in, const int* in_sizes, int n_in,
                              void* d_out, int out_size) {
    (void)in_sizes; (void)n_in; (void)out_size;
    const float* x    = (const float*)d_in[0];
    const float* cond = (const float*)d_in[1];
    const float* lniw = (const float*)d_in[2];
    const float* lnib = (const float*)d_in[3];
    const float* lnsw = (const float*)d_in[4];
    const float* lnsb = (const float*)d_in[5];
    const float* Wq   = (const float*)d_in[6];
    const float* Wk   = (const float*)d_in[7];
    const float* Wv   = (const float*)d_in[8];
    const float* wih  = (const float*)d_in[9];
    const float* whh  = (const float*)d_in[10];
    const float* bih  = (const float*)d_in[11];
    const float* bhh  = (const float*)d_in[12];

    float* out       = (float*)d_out;
    float* out_slots = out;                       // [64,8,256]
    float* out_last  = out + 131072;              // [64,8,4096]
    float* out_stack = out + 131072 + 2097152;    // [3,64,8,4096]

    cudaFuncSetAttribute(kv_hmma, cudaFuncAttributeMaxDynamicSharedMemorySize, KV_SMEM);

    prep_w<<<768, 256>>>(Wq, wih, whh);
    prep_b<<<512, 256>>>(Wk, Wv);
    ln_stats<<<ROWS/8, 256>>>(x);
    kv_hmma<<<2048, 256, KV_SMEM>>>(x, lniw, lnib);

    for (int it = 0; it < 3; it++) {
        slot_q<<<64, 256>>>(it, cond, lnsw, lnsb);
        dots_softmax<<<dim3(128, 64), 256>>>(out_stack + (size_t)it*2097152,
                                             (it == 2) ? out_last : (float*)0);
        upd_kernel<<<dim3(4, 4, 64), 256>>>();
        gru_kernel<<<128, 256>>>(it, cond, out_slots, bih, bhh);
    }
}

// round 13
// speedup vs baseline: 1.8511x; 1.1334x over previous
#include <cuda_runtime.h>
#include <cuda_fp16.h>
#include <math.h>

#define NB 64
#define NN 4096
#define ROWS (NB*NN)          // 262144
#define SCALE 0.125f
#define LN_EPS 1e-5f
#define SUM_EPS 1e-8f

// ---------------- device scratch (no allocations allowed) ----------------
__device__ float g_kT[(size_t)NB*256*NN];  // [b][d][j] transposed k (268MB)
__device__ float g_v [(size_t)ROWS*256];   // [row][d] v (268MB)
__device__ float g_WqT[256*256];
__device__ float g_WihT[256*768];
__device__ float g_WhhT[256*768];
__device__ float g_mu[ROWS];
__device__ float g_rs[ROWS];
__device__ float g_q[512*256];             // [(b*8+i)][h*64+d], pre-scaled
__device__ float g_attn[(size_t)NB*32*NN]; // [b][ih][j] softmaxed (pre-renorm)
__device__ float g_denom[NB*32];
__device__ float g_upd[512*256];
__device__ float g_slotsA[512*256];
__device__ float g_slotsB[512*256];
// row-major fp16 image of Wk|Wv: [o in 0..511][k in 0..255]
__device__ __align__(16) unsigned short g_B_img[512*256];

// ---------------- f32x2 packed-FMA helpers (Blackwell) ----------------
#define PK2(d,x,y)   asm("mov.b64 %0, {%1,%2};"          : "=l"(d) : "f"(x), "f"(y))
#define UPK2(x,y,d)  asm("mov.b64 {%0,%1}, %2;"          : "=f"(x), "=f"(y) : "l"(d))
#define FMA2(d,a,b,c) asm("fma.rn.f32x2 %0, %1, %2, %3;" : "=l"(d) : "l"(a), "l"(b), "l"(c))

// ---------------- baseline-PTX tensor-core helpers (sm_80+) ----------------
__device__ __forceinline__ unsigned smem_u32(const void* p) {
    unsigned a;
    asm("{ .reg .u64 t; cvta.to.shared.u64 t, %1; cvt.u32.u64 %0, t; }" : "=r"(a) : "l"(p));
    return a;
}
#define LDSM4(r, a) \
    asm volatile("ldmatrix.sync.aligned.m8n8.x4.shared.b16 {%0,%1,%2,%3}, [%4];" \
        : "=r"((r)[0]), "=r"((r)[1]), "=r"((r)[2]), "=r"((r)[3]) : "r"(a))
#define MMA16816(d, a, b) \
    asm volatile("mma.sync.aligned.m16n8k16.row.col.f32.f16.f16.f32 " \
        "{%0,%1,%2,%3},{%4,%5,%6,%7},{%8,%9},{%0,%1,%2,%3};" \
        : "+f"((d)[0]), "+f"((d)[1]), "+f"((d)[2]), "+f"((d)[3]) \
        : "r"((a)[0]), "r"((a)[1]), "r"((a)[2]), "r"((a)[3]), "r"((b)[0]), "r"((b)[1]))
#define CP_ASYNC16(dst, src) \
    asm volatile("cp.async.cg.shared.global [%0], [%1], 16;" :: "r"(dst), "l"(src))
#define CP_COMMIT() asm volatile("cp.async.commit_group;" ::: "memory")
#define CP_WAIT1()  asm volatile("cp.async.wait_group 1;"  ::: "memory")
#define CP_WAIT0()  asm volatile("cp.async.wait_group 0;"  ::: "memory")

// ---------------- prep: transpose weights (Wq / GRU) ----------------
__global__ void prep_w(const float* __restrict__ Wq, const float* __restrict__ wih,
                       const float* __restrict__ whh) {
    int idx = blockIdx.x*256 + threadIdx.x;          // < 196608
    if (idx < 256*256) {
        int d = idx >> 8, o = idx & 255;
        g_WqT[idx] = Wq[o*256 + d];
    }
    {
        int d = idx / 768, o = idx - d*768;
        g_WihT[idx] = wih[o*256 + d];
        g_WhhT[idx] = whh[o*256 + d];
    }
}

// ---------------- prep: fp16 image of Wk|Wv (plain row-major) --------
__global__ void prep_b(const float* __restrict__ Wk, const float* __restrict__ Wv) {
    int o = blockIdx.x, k = threadIdx.x;
    float w = (o < 256) ? Wk[o*256 + k] : Wv[(o-256)*256 + k];
    g_B_img[o*256 + k] = __half_as_ushort(__float2half_rn(w));
}

// ---------------- LayerNorm stats (warp per row) ----------------
__global__ void ln_stats(const float* __restrict__ x) {
    int row  = blockIdx.x*8 + (threadIdx.x >> 5);
    int lane = threadIdx.x & 31;
    const float4* xr = (const float4*)(x + (size_t)row*256);
    float s = 0.f, ss = 0.f;
#pragma unroll
    for (int i = 0; i < 2; i++) {
        float4 v = xr[lane + 32*i];
        s  += v.x + v.y + v.z + v.w;
        ss += v.x*v.x + v.y*v.y + v.z*v.z + v.w*v.w;
    }
#pragma unroll
    for (int o = 16; o; o >>= 1) {
        s  += __shfl_xor_sync(0xffffffffu, s,  o);
        ss += __shfl_xor_sync(0xffffffffu, ss, o);
    }
    if (lane == 0) {
        float mu  = s * (1.f/256.f);
        float var = ss * (1.f/256.f) - mu*mu;
        g_mu[row] = mu;
        g_rs[row] = rsqrtf(var + LN_EPS);
    }
}

// ---------------- HMMA K/V GEMM fragments (fp16 2-term A-split) ----------
struct Frags {
    unsigned a0[4], a1[4], l0[4], l1[4];   // A hi (2 m-tiles), A lo (2 m-tiles)
    unsigned bh[8];                        // B (2 n-sub-tiles)
};

__device__ __forceinline__ void load_frags(
    Frags& f, int ks, int half, unsigned buf,
    unsigned aBase0, unsigned aBase1, unsigned klA, unsigned xA,
    unsigned nB0row, unsigned nB1row, unsigned kbB, unsigned xB)
{
    unsigned kgA = (unsigned)(half*8 + ks)*2u + klA;
    unsigned aoff = ((kgA ^ xA) << 4);
    LDSM4(f.a0, aBase0 + aoff);
    LDSM4(f.a1, aBase1 + aoff);
    LDSM4(f.l0, aBase0 + 65536u + aoff);
    LDSM4(f.l1, aBase1 + 65536u + aoff);
    unsigned kgB = (unsigned)ks*2u + kbB;
    LDSM4(&f.bh[0], buf + nB0row + ((kgB ^ xB) << 4));
    LDSM4(&f.bh[4], buf + nB1row + ((kgB ^ xB) << 4));
}

__device__ __forceinline__ void do_mmas(float acc[2][4][4], const Frags& f) {
#pragma unroll
    for (int j = 0; j < 4; j++) {
        MMA16816(acc[0][j], f.a0, &f.bh[j*2]);
        MMA16816(acc[1][j], f.a1, &f.bh[j*2]);
    }
#pragma unroll
    for (int j = 0; j < 4; j++) {
        MMA16816(acc[0][j], f.l0, &f.bh[j*2]);
        MMA16816(acc[1][j], f.l1, &f.bh[j*2]);
    }
}

// ---------------- HMMA K/V GEMM: [262144,256] @ [256,512], fp16 2-term ----
// CTA = 128 rows x 512 outputs. A (hi+lo fp16) resident; B streamed in 16
// chunks (nb 0..7 x k-half 0..1) of 16KB via cp.async double buffering.
// smem: A_hi [0,64K) A_lo [64K,128K) Bbuf0 [128K,144K) Bbuf1 [144K,160K)
#define KV_SMEM 163840

__global__ void __launch_bounds__(256, 1)
kv_hmma(const float* __restrict__ x, const float* __restrict__ lw,
        const float* __restrict__ lb) {
    extern __shared__ char smem[];
    __shared__ float smu[128], srs[128];

    const unsigned sb  = smem_u32(smem);
    const unsigned sbB = sb + 131072u;
    int tid = threadIdx.x, wid = tid >> 5, lane = tid & 31;
    int m0 = blockIdx.x * 128;
    int bidx = m0 >> 12;           // batch of this CTA (128 | 4096)
    int jr   = m0 & 4095;          // j base within batch

    if (tid < 128) { smu[tid] = g_mu[m0 + tid]; srs[tid] = g_rs[m0 + tid]; }

    // ---- prefetch B chunk 0 into buffer 0 (16KB = 1024 float4) ----
    {
#pragma unroll
        for (int it = 0; it < 4; it++) {
            int u = tid + it*256;
            int o = u >> 4, g = u & 15;
            const char* src = (const char*)g_B_img + (size_t)o*512 + g*16;
            unsigned dst = sbB + o*256 + ((unsigned)(g ^ (o & 7)) << 4);
            CP_ASYNC16(dst, src);
        }
        CP_COMMIT();
    }
    __syncthreads();   // smu/srs visible

    // ---- load A with fused LN, split into fp16 hi/lo, swizzled ----
    {
        int cpair = tid & 127;            // column pair index
        int c2 = cpair * 2;
        int rbase = (tid >> 7) * 64;
        float w0 = lw[c2], w1 = lw[c2+1], bb0 = lb[c2], bb1 = lb[c2+1];
        unsigned gA = (unsigned)(cpair >> 2);
        unsigned boff = (unsigned)(cpair & 3) * 4u;
#pragma unroll 4
        for (int r = 0; r < 64; r++) {
            int row = rbase + r;
            float2 xv = *(const float2*)&x[(size_t)(m0 + row)*256 + c2];
            float mu = smu[row], rs = srs[row];
            float v0 = (xv.x - mu)*rs*w0 + bb0;
            float v1 = (xv.y - mu)*rs*w1 + bb1;
            __half h0 = __float2half_rn(v0);
            __half h1 = __float2half_rn(v1);
            __half l0 = __float2half_rn(v0 - __half2float(h0));
            __half l1 = __float2half_rn(v1 - __half2float(h1));
            unsigned hp = (unsigned)__half_as_ushort(h0) |
                          ((unsigned)__half_as_ushort(h1) << 16);
            unsigned lp = (unsigned)__half_as_ushort(l0) |
                          ((unsigned)__half_as_ushort(l1) << 16);
            unsigned phys = (unsigned)row*512u + ((gA ^ (unsigned)(row & 7)) << 4) + boff;
            *(unsigned*)(smem + phys)          = hp;
            *(unsigned*)(smem + 65536 + phys)  = lp;
        }
    }

    // ---- warp tiling: 4 M-warps x 2 N-warps, warp tile m32 x n32 ----
    int mw = wid >> 1, nw = wid & 1;
    int rA0 = mw*32 + (lane & 15);
    int rA1 = rA0 + 16;
    unsigned klA = (unsigned)(lane >> 4);
    unsigned xA = (unsigned)(rA0 & 7);
    unsigned aBase0 = sb + (unsigned)rA0*512u;
    unsigned aBase1 = sb + (unsigned)rA1*512u;

    int nB0 = nw*32 + (lane & 7) + ((lane >> 4) & 1)*8;
    int nB1 = nB0 + 16;
    unsigned nB0row = (unsigned)nB0*256u;
    unsigned nB1row = (unsigned)nB1*256u;
    unsigned kbB = (unsigned)((lane >> 3) & 1);
    unsigned xB = (unsigned)(nB0 & 7);

    float acc[2][4][4];
#pragma unroll
    for (int i = 0; i < 2; i++)
#pragma unroll
        for (int j = 0; j < 4; j++)
#pragma unroll
            for (int q = 0; q < 4; q++) acc[i][j][q] = 0.f;

    for (int c = 0; c < 16; c++) {
        if (c + 1 < 16) {
            int nbn = (c + 1) >> 1, halfn = (c + 1) & 1;
            unsigned bufn = sbB + (unsigned)((c + 1) & 1)*16384u;
#pragma unroll
            for (int it = 0; it < 4; it++) {
                int u = tid + it*256;
                int o = u >> 4, g = u & 15;
                const char* src = (const char*)g_B_img
                    + (size_t)(nbn*64 + o)*512 + halfn*256 + g*16;
                unsigned dst = bufn + o*256 + ((unsigned)(g ^ (o & 7)) << 4);
                CP_ASYNC16(dst, src);
            }
            CP_COMMIT();
            CP_WAIT1();
        } else {
            CP_WAIT0();
        }
        __syncthreads();

        unsigned buf = sbB + (unsigned)(c & 1)*16384u;
        int half = c & 1;

        Frags fr0, fr1;
        load_frags(fr0, 0, half, buf, aBase0, aBase1, klA, xA,
                   nB0row, nB1row, kbB, xB);
#pragma unroll
        for (int ks = 0; ks < 8; ks++) {
            Frags& cur = (ks & 1) ? fr1 : fr0;
            Frags& nxt = (ks & 1) ? fr0 : fr1;
            if (ks < 7)
                load_frags(nxt, ks + 1, half, buf, aBase0, aBase1, klA, xA,
                           nB0row, nB1row, kbB, xB);
            do_mmas(acc, cur);
        }

        if (c & 1) {
            int nbidx = c >> 1;
#pragma unroll
            for (int i = 0; i < 2; i++) {
#pragma unroll
                for (int j = 0; j < 4; j++) {
                    int row = mw*32 + i*16 + (lane >> 2);
                    int col = nbidx*64 + nw*32 + j*8 + (lane & 3)*2;
                    if (nbidx < 4) {
                        // k: write transposed g_kT[b][col][jr+row]
                        float* p0 = &g_kT[((size_t)(bidx*256 + col))*4096 + jr + row];
                        p0[0]      = acc[i][j][0];
                        p0[4096]   = acc[i][j][1];
                        p0[8]      = acc[i][j][2];
                        p0[4104]   = acc[i][j][3];
                    } else {
                        int vc = col - 256;
                        float2 o0 = {acc[i][j][0], acc[i][j][1]};
                        float2 o1 = {acc[i][j][2], acc[i][j][3]};
                        *(float2*)&g_v[(size_t)(m0 + row)*256 + vc]     = o0;
                        *(float2*)&g_v[(size_t)(m0 + row + 8)*256 + vc] = o1;
                    }
                    acc[i][j][0] = acc[i][j][1] = acc[i][j][2] = acc[i][j][3] = 0.f;
                }
            }
        }
        __syncthreads();
    }
}

// ---------------- slot LN + q projection (+ zero denom) ----------------
__global__ void __launch_bounds__(256)
slot_q(int it, const float* __restrict__ cond,
       const float* __restrict__ lw, const float* __restrict__ lb) {
    const float* src = (it == 0) ? cond : (it == 1 ? g_slotsA : g_slotsB);
    int b = blockIdx.x, t = threadIdx.x, wid = t >> 5, lane = t & 31;

    __shared__ float sn[8][256];
    __shared__ float wt[32][256];

    const float4* row = (const float4*)(src + (size_t)(b*8 + wid)*256);
    float4 v0 = row[lane], v1 = row[lane + 32];
    float s  = v0.x + v0.y + v0.z + v0.w + v1.x + v1.y + v1.z + v1.w;
    float ss = v0.x*v0.x + v0.y*v0.y + v0.z*v0.z + v0.w*v0.w
             + v1.x*v1.x + v1.y*v1.y + v1.z*v1.z + v1.w*v1.w;
#pragma unroll
    for (int o = 16; o; o >>= 1) {
        s  += __shfl_xor_sync(0xffffffffu, s,  o);
        ss += __shfl_xor_sync(0xffffffffu, ss, o);
    }
    float mu = s * (1.f/256.f);
    float rs = rsqrtf(ss * (1.f/256.f) - mu*mu + LN_EPS);
#pragma unroll
    for (int i = 0; i < 2; i++) {
        float4 xv = i ? v1 : v0;
        int c = (lane + 32*i) * 4;
        float4 w4 = *(const float4*)&lw[c];
        float4 b4 = *(const float4*)&lb[c];
        sn[wid][c+0] = (xv.x - mu)*rs*w4.x + b4.x;
        sn[wid][c+1] = (xv.y - mu)*rs*w4.y + b4.y;
        sn[wid][c+2] = (xv.z - mu)*rs*w4.z + b4.z;
        sn[wid][c+3] = (xv.w - mu)*rs*w4.w + b4.w;
    }
    if (t < 32) g_denom[b*32 + t] = 0.f;
    __syncthreads();

    float acc[8] = {0,0,0,0,0,0,0,0};
    for (int d0 = 0; d0 < 256; d0 += 32) {
        __syncthreads();
#pragma unroll
        for (int i = 0; i < 8; i++) {
            int u = t + i*256;
            int dd = u >> 6, g = u & 63;
            *(float4*)&wt[dd][g*4] = *(const float4*)&g_WqT[(d0 + dd)*256 + g*4];
        }
        __syncthreads();
#pragma unroll 4
        for (int dd = 0; dd < 32; dd++) {
            float w = wt[dd][t];
#pragma unroll
            for (int r = 0; r < 8; r++) acc[r] += sn[r][d0 + dd] * w;
        }
    }
#pragma unroll
    for (int r = 0; r < 8; r++) g_q[(size_t)(b*8 + r)*256 + t] = acc[r] * SCALE;
}

// ---------------- dots + softmax: thread-per-j, no shfl in hot path --------
// grid (16, 64): block handles j in [jt*256, jt*256+256) of batch b.
__global__ void __launch_bounds__(256)
dots_softmax(float* __restrict__ out_stack, float* __restrict__ out_last) {
    int b = blockIdx.y, jt = blockIdx.x;
    int tid = threadIdx.x, lane = tid & 31;
    int j = jt*256 + tid;

    // qs2[hd*8 + p*2 + half] = q[b][2p+half][hd]  (i-pairs packed for FMA2)
    __shared__ float qs2[2048];
    __shared__ float den_s[32];

#pragma unroll
    for (int r = 0; r < 8; r++) {
        int u = r*256 + tid;
        int hd = u >> 3, p = (u >> 1) & 3, hf = u & 1;
        qs2[u] = g_q[(size_t)(b*8 + 2*p + hf)*256 + hd];
    }
    if (tid < 128) g_upd[b*2048 + jt*128 + tid] = 0.f;
    if (tid < 32) den_s[tid] = 0.f;
    __syncthreads();

    // dots accumulation: accp[p*4+h] = {dots[2p][h], dots[2p+1][h]} packed
    unsigned long long accp[16];
#pragma unroll
    for (int i = 0; i < 16; i++) accp[i] = 0ull;

    const float* kbase = g_kT + (size_t)b*256*4096 + j;
#pragma unroll
    for (int h = 0; h < 4; h++) {
#pragma unroll 8
        for (int d = 0; d < 64; d++) {
            int hd = h*64 + d;
            float kv = kbase[(size_t)hd*4096];
            unsigned long long kp; PK2(kp, kv, kv);
#pragma unroll
            for (int p = 0; p < 4; p++) {
                unsigned long long qv = *(unsigned long long*)&qs2[hd*8 + p*2];
                FMA2(accp[p*4 + h], kp, qv, accp[p*4 + h]);
            }
        }
    }

    float e[32];
#pragma unroll
    for (int p = 0; p < 4; p++)
#pragma unroll
        for (int h = 0; h < 4; h++)
            UPK2(e[(2*p)*4 + h], e[(2*p+1)*4 + h], accp[p*4 + h]);

    float mx = e[0];
#pragma unroll
    for (int i = 1; i < 32; i++) mx = fmaxf(mx, e[i]);
    float ssum = 0.f;
#pragma unroll
    for (int i = 0; i < 32; i++) { e[i] = __expf(e[i] - mx); ssum += e[i]; }
    float inv = 1.f / ssum;
#pragma unroll
    for (int i = 0; i < 32; i++) e[i] *= inv;

    // per-ih denominators: warp-reduce then smem/global atomics
#pragma unroll
    for (int i = 0; i < 32; i++) {
        float v = e[i];
        v += __shfl_xor_sync(0xffffffffu, v, 1);
        v += __shfl_xor_sync(0xffffffffu, v, 2);
        v += __shfl_xor_sync(0xffffffffu, v, 4);
        v += __shfl_xor_sync(0xffffffffu, v, 8);
        v += __shfl_xor_sync(0xffffffffu, v, 16);
        if (lane == 0) atomicAdd(&den_s[i], v);
    }
    __syncthreads();
    if (tid < 32) atomicAdd(&g_denom[b*32 + tid], den_s[tid]);

    // coalesced writes: attn (pre-renorm) + head-mean outputs
#pragma unroll
    for (int ih = 0; ih < 32; ih++)
        g_attn[(size_t)(b*32 + ih)*NN + j] = e[ih];
#pragma unroll
    for (int i = 0; i < 8; i++) {
        float ms = 0.25f*(e[i*4] + e[i*4+1] + e[i*4+2] + e[i*4+3]);
        size_t o = (size_t)(b*8 + i)*NN + j;
        out_stack[o] = ms;
        if (out_last) out_last[o] = ms;
    }
}

// ---------------- updates = (attn/denom) @ v ----------------
__global__ void __launch_bounds__(256)
upd_kernel() {
    int chunk = blockIdx.x, h = blockIdx.y, b = blockIdx.z;
    int tid = threadIdx.x;
    int d = tid & 63, js = tid >> 6;
    __shared__ float at_s[8][128];
    __shared__ float dinv[8];
    if (tid < 8) dinv[tid] = 1.f / (g_denom[b*32 + tid*4 + h] + SUM_EPS);
    float acc[8];
#pragma unroll
    for (int i = 0; i < 8; i++) acc[i] = 0.f;
    int j0 = chunk * 1024;
    for (int sc = 0; sc < 8; sc++) {
        __syncthreads();
#pragma unroll
        for (int r = 0; r < 4; r++) {
            int idx = r*256 + tid; int i = idx >> 7, jc = idx & 127;
            at_s[i][jc] = g_attn[(size_t)(b*32 + i*4 + h)*NN + j0 + sc*128 + jc];
        }
        __syncthreads();
#pragma unroll 8
        for (int jj = 0; jj < 32; jj++) {
            int jl = jj*4 + js;
            float vv = g_v[(size_t)(b*NN + j0 + sc*128 + jl)*256 + h*64 + d];
#pragma unroll
            for (int i = 0; i < 8; i++) acc[i] += vv * at_s[i][jl];
        }
    }
#pragma unroll
    for (int i = 0; i < 8; i++)
        atomicAdd(&g_upd[(b*8 + i)*256 + h*64 + d], acc[i] * dinv[i]);
}

// ---------------- GRU cell (4 rows per block for weight reuse) ----------------
__global__ void __launch_bounds__(256)
gru_kernel(int it, const float* __restrict__ cond, float* __restrict__ out_slots,
           const float* __restrict__ bih, const float* __restrict__ bhh) {
    const float* hsrc = (it == 0) ? cond : (it == 1 ? g_slotsA : g_slotsB);
    float* dst = (it == 0) ? g_slotsA : (it == 1 ? g_slotsB : out_slots);
    int t = threadIdx.x;
    __shared__ float u_s[4][256], h_s[4][256];
#pragma unroll
    for (int r = 0; r < 4; r++) {
        int row = blockIdx.x*4 + r;
        u_s[r][t] = g_upd[row*256 + t];
        h_s[r][t] = hsrc[row*256 + t];
    }
    __syncthreads();
    float axr[4] = {0,0,0,0}, axz[4] = {0,0,0,0}, axn[4] = {0,0,0,0};
    float ahr[4] = {0,0,0,0}, ahz[4] = {0,0,0,0}, ahn[4] = {0,0,0,0};
#pragma unroll 2
    for (int dd = 0; dd < 256; dd++) {
        float wr = g_WihT[dd*768 + t],       wz = g_WihT[dd*768 + 256 + t];
        float wn = g_WihT[dd*768 + 512 + t];
        float vr = g_WhhT[dd*768 + t],       vz = g_WhhT[dd*768 + 256 + t];
        float vn = g_WhhT[dd*768 + 512 + t];
#pragma unroll
        for (int r = 0; r < 4; r++) {
            float u = u_s[r][dd], hh = h_s[r][dd];
            axr[r] += u*wr;  axz[r] += u*wz;  axn[r] += u*wn;
            ahr[r] += hh*vr; ahz[r] += hh*vz; ahn[r] += hh*vn;
        }
    }
    float br = bih[t], bz = bih[256 + t], bn = bih[512 + t];
    float cr = bhh[t], cz = bhh[256 + t], cn = bhh[512 + t];
#pragma unroll
    for (int r = 0; r < 4; r++) {
        float rg = 1.f / (1.f + __expf(-(axr[r] + ahr[r] + br + cr)));
        float zg = 1.f / (1.f + __expf(-(axz[r] + ahz[r] + bz + cz)));
        float ng = tanhf(axn[r] + bn + rg*(ahn[r] + cn));
        int row = blockIdx.x*4 + r;
        dst[row*256 + t] = (1.f - zg)*ng + zg*h_s[r][t];
    }
}

// ---------------- launch ----------------
extern "C" void kernel_launch(void* const* d_in, const int* in_sizes, int n_in,
                              void* d_out, int out_size) {
    (void)in_sizes; (void)n_in; (void)out_size;
    const float* x    = (const float*)d_in[0];
    const float* cond = (const float*)d_in[1];
    const float* lniw = (const float*)d_in[2];
    const float* lnib = (const float*)d_in[3];
    const float* lnsw = (const float*)d_in[4];
    const float* lnsb = (const float*)d_in[5];
    const float* Wq   = (const float*)d_in[6];
    const float* Wk   = (const float*)d_in[7];
    const float* Wv   = (const float*)d_in[8];
    const float* wih  = (const float*)d_in[9];
    const float* whh  = (const float*)d_in[10];
    const float* bih  = (const float*)d_in[11];
    const float* bhh  = (const float*)d_in[12];

    float* out       = (float*)d_out;
    float* out_slots = out;                       // [64,8,256]
    float* out_last  = out + 131072;              // [64,8,4096]
    float* out_stack = out + 131072 + 2097152;    // [3,64,8,4096]

    cudaFuncSetAttribute(kv_hmma, cudaFuncAttributeMaxDynamicSharedMemorySize, KV_SMEM);

    prep_w<<<768, 256>>>(Wq, wih, whh);
    prep_b<<<512, 256>>>(Wk, Wv);
    ln_stats<<<ROWS/8, 256>>>(x);
    kv_hmma<<<2048, 256, KV_SMEM>>>(x, lniw, lnib);

    for (int it = 0; it < 3; it++) {
        slot_q<<<64, 256>>>(it, cond, lnsw, lnsb);
        dots_softmax<<<dim3(16, 64), 256>>>(out_stack + (size_t)it*2097152,
                                            (it == 2) ? out_last : (float*)0);
        upd_kernel<<<dim3(4, 4, 64), 256>>>();
        gru_kernel<<<128, 256>>>(it, cond, out_slots, bih, bhh);
    }
}

// round 14
// speedup vs baseline: 2.2206x; 1.1996x over previous
#include <cuda_runtime.h>
#include <cuda_fp16.h>
#include <math.h>

#define NB 64
#define NN 4096
#define ROWS (NB*NN)          // 262144
#define SCALE 0.125f
#define LN_EPS 1e-5f
#define SUM_EPS 1e-8f

// ---------------- device scratch (no allocations allowed) ----------------
__device__ float g_kT[(size_t)NB*256*NN];  // [b][d][j] transposed k (268MB)
__device__ float g_v [(size_t)ROWS*256];   // [row][d] v (268MB)
__device__ float g_WqT[256*256];
__device__ float g_WihT[256*768];
__device__ float g_WhhT[256*768];
__device__ float g_q[512*256];             // [(b*8+i)][h*64+d], pre-scaled
__device__ float g_attn[(size_t)NB*32*NN]; // [b][ih][j] softmaxed (pre-renorm)
__device__ float g_denom[NB*32];
__device__ float g_upd[512*256];
__device__ float g_slotsA[512*256];
__device__ float g_slotsB[512*256];
// row-major fp16 image of Wk|Wv: [o in 0..511][k in 0..255]
__device__ __align__(16) unsigned short g_B_img[512*256];

// ---------------- f32x2 packed-FMA helpers (Blackwell) ----------------
#define PK2(d,x,y)   asm("mov.b64 %0, {%1,%2};"          : "=l"(d) : "f"(x), "f"(y))
#define UPK2(x,y,d)  asm("mov.b64 {%0,%1}, %2;"          : "=f"(x), "=f"(y) : "l"(d))
#define FMA2(d,a,b,c) asm("fma.rn.f32x2 %0, %1, %2, %3;" : "=l"(d) : "l"(a), "l"(b), "l"(c))

// ---------------- baseline-PTX tensor-core helpers (sm_80+) ----------------
__device__ __forceinline__ unsigned smem_u32(const void* p) {
    unsigned a;
    asm("{ .reg .u64 t; cvta.to.shared.u64 t, %1; cvt.u32.u64 %0, t; }" : "=r"(a) : "l"(p));
    return a;
}
#define LDSM4(r, a) \
    asm volatile("ldmatrix.sync.aligned.m8n8.x4.shared.b16 {%0,%1,%2,%3}, [%4];" \
        : "=r"((r)[0]), "=r"((r)[1]), "=r"((r)[2]), "=r"((r)[3]) : "r"(a))
#define MMA16816(d, a, b) \
    asm volatile("mma.sync.aligned.m16n8k16.row.col.f32.f16.f16.f32 " \
        "{%0,%1,%2,%3},{%4,%5,%6,%7},{%8,%9},{%0,%1,%2,%3};" \
        : "+f"((d)[0]), "+f"((d)[1]), "+f"((d)[2]), "+f"((d)[3]) \
        : "r"((a)[0]), "r"((a)[1]), "r"((a)[2]), "r"((a)[3]), "r"((b)[0]), "r"((b)[1]))
#define CP_ASYNC16(dst, src) \
    asm volatile("cp.async.cg.shared.global [%0], [%1], 16;" :: "r"(dst), "l"(src))
#define CP_COMMIT() asm volatile("cp.async.commit_group;" ::: "memory")
#define CP_WAIT1()  asm volatile("cp.async.wait_group 1;"  ::: "memory")
#define CP_WAIT0()  asm volatile("cp.async.wait_group 0;"  ::: "memory")

// ---------------- prep: transpose weights (Wq / GRU) ----------------
__global__ void prep_w(const float* __restrict__ Wq, const float* __restrict__ wih,
                       const float* __restrict__ whh) {
    int idx = blockIdx.x*256 + threadIdx.x;          // < 196608
    if (idx < 256*256) {
        int d = idx >> 8, o = idx & 255;
        g_WqT[idx] = Wq[o*256 + d];
    }
    {
        int d = idx / 768, o = idx - d*768;
        g_WihT[idx] = wih[o*256 + d];
        g_WhhT[idx] = whh[o*256 + d];
    }
}

// ---------------- prep: fp16 image of Wk|Wv (plain row-major) --------
__global__ void prep_b(const float* __restrict__ Wk, const float* __restrict__ Wv) {
    int o = blockIdx.x, k = threadIdx.x;
    float w = (o < 256) ? Wk[o*256 + k] : Wv[(o-256)*256 + k];
    g_B_img[o*256 + k] = __half_as_ushort(__float2half_rn(w));
}

// ---------------- HMMA K/V GEMM fragments (pure fp16) ----------
struct Frags {
    unsigned a0[4], a1[4];   // A (2 m-tiles)
    unsigned bh[8];          // B (2 n-sub-tiles)
};

__device__ __forceinline__ void load_frags(
    Frags& f, int ks, int half, unsigned buf,
    unsigned aBase0, unsigned aBase1, unsigned klA, unsigned xA,
    unsigned nB0row, unsigned nB1row, unsigned kbB, unsigned xB)
{
    unsigned kgA = (unsigned)(half*8 + ks)*2u + klA;
    unsigned aoff = ((kgA ^ xA) << 4);
    LDSM4(f.a0, aBase0 + aoff);
    LDSM4(f.a1, aBase1 + aoff);
    unsigned kgB = (unsigned)ks*2u + kbB;
    LDSM4(&f.bh[0], buf + nB0row + ((kgB ^ xB) << 4));
    LDSM4(&f.bh[4], buf + nB1row + ((kgB ^ xB) << 4));
}

__device__ __forceinline__ void do_mmas(float acc[2][4][4], const Frags& f) {
#pragma unroll
    for (int j = 0; j < 4; j++) {
        MMA16816(acc[0][j], f.a0, &f.bh[j*2]);
        MMA16816(acc[1][j], f.a1, &f.bh[j*2]);
    }
}

// ---------------- HMMA K/V GEMM: [262144,256] @ [256,512], fp16 ----
// CTA = 128 rows x 512 outputs, 2 CTAs/SM. LN stats computed inline.
// A fp16 resident; B streamed in 16 chunks of 16KB via cp.async dbl-buffer.
// smem: A [0,64K) Bbuf0 [64K,80K) Bbuf1 [80K,96K)
#define KV_SMEM 98304

__global__ void __launch_bounds__(256, 2)
kv_hmma(const float* __restrict__ x, const float* __restrict__ lw,
        const float* __restrict__ lb) {
    extern __shared__ char smem[];
    __shared__ float smu[128], srs[128];

    const unsigned sb  = smem_u32(smem);
    const unsigned sbB = sb + 65536u;
    int tid = threadIdx.x, wid = tid >> 5, lane = tid & 31;
    int m0 = blockIdx.x * 128;
    int bidx = m0 >> 12;           // batch of this CTA (128 | 4096)
    int jr   = m0 & 4095;          // j base within batch

    // ---- prefetch B chunk 0 into buffer 0 (16KB = 1024 float4) ----
    {
#pragma unroll
        for (int it = 0; it < 4; it++) {
            int u = tid + it*256;
            int o = u >> 4, g = u & 15;
            const char* src = (const char*)g_B_img + (size_t)o*512 + g*16;
            unsigned dst = sbB + o*256 + ((unsigned)(g ^ (o & 7)) << 4);
            CP_ASYNC16(dst, src);
        }
        CP_COMMIT();
    }

    // ---- inline LN stats: warp wid handles rows wid*16 .. wid*16+15 ----
#pragma unroll 2
    for (int r = 0; r < 16; r++) {
        int row = wid*16 + r;
        const float4* xr = (const float4*)(x + (size_t)(m0 + row)*256);
        float4 v0 = xr[lane*2], v1 = xr[lane*2 + 1];
        float s  = v0.x + v0.y + v0.z + v0.w + v1.x + v1.y + v1.z + v1.w;
        float ss = v0.x*v0.x + v0.y*v0.y + v0.z*v0.z + v0.w*v0.w
                 + v1.x*v1.x + v1.y*v1.y + v1.z*v1.z + v1.w*v1.w;
#pragma unroll
        for (int o = 16; o; o >>= 1) {
            s  += __shfl_xor_sync(0xffffffffu, s,  o);
            ss += __shfl_xor_sync(0xffffffffu, ss, o);
        }
        if (lane == 0) {
            float mu = s * (1.f/256.f);
            smu[row] = mu;
            srs[row] = rsqrtf(ss * (1.f/256.f) - mu*mu + LN_EPS);
        }
    }
    __syncthreads();

    // ---- load A with fused LN, fp16, swizzled ----
    {
        int cpair = tid & 127;            // column pair index
        int c2 = cpair * 2;
        int rbase = (tid >> 7) * 64;
        float w0 = lw[c2], w1 = lw[c2+1], bb0 = lb[c2], bb1 = lb[c2+1];
        unsigned gA = (unsigned)(cpair >> 2);
        unsigned boff = (unsigned)(cpair & 3) * 4u;
#pragma unroll 4
        for (int r = 0; r < 64; r++) {
            int row = rbase + r;
            float2 xv = *(const float2*)&x[(size_t)(m0 + row)*256 + c2];
            float mu = smu[row], rs = srs[row];
            float v0 = (xv.x - mu)*rs*w0 + bb0;
            float v1 = (xv.y - mu)*rs*w1 + bb1;
            unsigned hp = (unsigned)__half_as_ushort(__float2half_rn(v0)) |
                          ((unsigned)__half_as_ushort(__float2half_rn(v1)) << 16);
            unsigned phys = (unsigned)row*512u + ((gA ^ (unsigned)(row & 7)) << 4) + boff;
            *(unsigned*)(smem + phys) = hp;
        }
    }

    // ---- warp tiling: 4 M-warps x 2 N-warps, warp tile m32 x n32 ----
    int mw = wid >> 1, nw = wid & 1;
    int rA0 = mw*32 + (lane & 15);
    int rA1 = rA0 + 16;
    unsigned klA = (unsigned)(lane >> 4);
    unsigned xA = (unsigned)(rA0 & 7);
    unsigned aBase0 = sb + (unsigned)rA0*512u;
    unsigned aBase1 = sb + (unsigned)rA1*512u;

    int nB0 = nw*32 + (lane & 7) + ((lane >> 4) & 1)*8;
    int nB1 = nB0 + 16;
    unsigned nB0row = (unsigned)nB0*256u;
    unsigned nB1row = (unsigned)nB1*256u;
    unsigned kbB = (unsigned)((lane >> 3) & 1);
    unsigned xB = (unsigned)(nB0 & 7);

    float acc[2][4][4];
#pragma unroll
    for (int i = 0; i < 2; i++)
#pragma unroll
        for (int j = 0; j < 4; j++)
#pragma unroll
            for (int q = 0; q < 4; q++) acc[i][j][q] = 0.f;

    for (int c = 0; c < 16; c++) {
        if (c + 1 < 16) {
            int nbn = (c + 1) >> 1, halfn = (c + 1) & 1;
            unsigned bufn = sbB + (unsigned)((c + 1) & 1)*16384u;
#pragma unroll
            for (int it = 0; it < 4; it++) {
                int u = tid + it*256;
                int o = u >> 4, g = u & 15;
                const char* src = (const char*)g_B_img
                    + (size_t)(nbn*64 + o)*512 + halfn*256 + g*16;
                unsigned dst = bufn + o*256 + ((unsigned)(g ^ (o & 7)) << 4);
                CP_ASYNC16(dst, src);
            }
            CP_COMMIT();
            CP_WAIT1();
        } else {
            CP_WAIT0();
        }
        __syncthreads();

        unsigned buf = sbB + (unsigned)(c & 1)*16384u;
        int half = c & 1;

        Frags fr0, fr1;
        load_frags(fr0, 0, half, buf, aBase0, aBase1, klA, xA,
                   nB0row, nB1row, kbB, xB);
#pragma unroll
        for (int ks = 0; ks < 8; ks++) {
            Frags& cur = (ks & 1) ? fr1 : fr0;
            Frags& nxt = (ks & 1) ? fr0 : fr1;
            if (ks < 7)
                load_frags(nxt, ks + 1, half, buf, aBase0, aBase1, klA, xA,
                           nB0row, nB1row, kbB, xB);
            do_mmas(acc, cur);
        }

        if (c & 1) {
            int nbidx = c >> 1;
#pragma unroll
            for (int i = 0; i < 2; i++) {
#pragma unroll
                for (int j = 0; j < 4; j++) {
                    int row = mw*32 + i*16 + (lane >> 2);
                    int col = nbidx*64 + nw*32 + j*8 + (lane & 3)*2;
                    if (nbidx < 4) {
                        // k: write transposed g_kT[b][col][jr+row]
                        float* p0 = &g_kT[((size_t)(bidx*256 + col))*4096 + jr + row];
                        p0[0]      = acc[i][j][0];
                        p0[4096]   = acc[i][j][1];
                        p0[8]      = acc[i][j][2];
                        p0[4104]   = acc[i][j][3];
                    } else {
                        int vc = col - 256;
                        float2 o0 = {acc[i][j][0], acc[i][j][1]};
                        float2 o1 = {acc[i][j][2], acc[i][j][3]};
                        *(float2*)&g_v[(size_t)(m0 + row)*256 + vc]     = o0;
                        *(float2*)&g_v[(size_t)(m0 + row + 8)*256 + vc] = o1;
                    }
                    acc[i][j][0] = acc[i][j][1] = acc[i][j][2] = acc[i][j][3] = 0.f;
                }
            }
        }
        __syncthreads();
    }
}

// ---------------- slot LN + q projection (+ zero denom) ----------------
__global__ void __launch_bounds__(256)
slot_q(int it, const float* __restrict__ cond,
       const float* __restrict__ lw, const float* __restrict__ lb) {
    const float* src = (it == 0) ? cond : (it == 1 ? g_slotsA : g_slotsB);
    int b = blockIdx.x, t = threadIdx.x, wid = t >> 5, lane = t & 31;

    __shared__ float sn[8][256];
    __shared__ float wt[32][256];

    const float4* row = (const float4*)(src + (size_t)(b*8 + wid)*256);
    float4 v0 = row[lane], v1 = row[lane + 32];
    float s  = v0.x + v0.y + v0.z + v0.w + v1.x + v1.y + v1.z + v1.w;
    float ss = v0.x*v0.x + v0.y*v0.y + v0.z*v0.z + v0.w*v0.w
             + v1.x*v1.x + v1.y*v1.y + v1.z*v1.z + v1.w*v1.w;
#pragma unroll
    for (int o = 16; o; o >>= 1) {
        s  += __shfl_xor_sync(0xffffffffu, s,  o);
        ss += __shfl_xor_sync(0xffffffffu, ss, o);
    }
    float mu = s * (1.f/256.f);
    float rs = rsqrtf(ss * (1.f/256.f) - mu*mu + LN_EPS);
#pragma unroll
    for (int i = 0; i < 2; i++) {
        float4 xv = i ? v1 : v0;
        int c = (lane + 32*i) * 4;
        float4 w4 = *(const float4*)&lw[c];
        float4 b4 = *(const float4*)&lb[c];
        sn[wid][c+0] = (xv.x - mu)*rs*w4.x + b4.x;
        sn[wid][c+1] = (xv.y - mu)*rs*w4.y + b4.y;
        sn[wid][c+2] = (xv.z - mu)*rs*w4.z + b4.z;
        sn[wid][c+3] = (xv.w - mu)*rs*w4.w + b4.w;
    }
    if (t < 32) g_denom[b*32 + t] = 0.f;
    __syncthreads();

    float acc[8] = {0,0,0,0,0,0,0,0};
    for (int d0 = 0; d0 < 256; d0 += 32) {
        __syncthreads();
#pragma unroll
        for (int i = 0; i < 8; i++) {
            int u = t + i*256;
            int dd = u >> 6, g = u & 63;
            *(float4*)&wt[dd][g*4] = *(const float4*)&g_WqT[(d0 + dd)*256 + g*4];
        }
        __syncthreads();
#pragma unroll 4
        for (int dd = 0; dd < 32; dd++) {
            float w = wt[dd][t];
#pragma unroll
            for (int r = 0; r < 8; r++) acc[r] += sn[r][d0 + dd] * w;
        }
    }
#pragma unroll
    for (int r = 0; r < 8; r++) g_q[(size_t)(b*8 + r)*256 + t] = acc[r] * SCALE;
}

// ---------------- dots + softmax: thread-per-j, no shfl in hot path --------
// grid (16, 64): block handles j in [jt*256, jt*256+256) of batch b.
__global__ void __launch_bounds__(256)
dots_softmax(float* __restrict__ out_stack, float* __restrict__ out_last) {
    int b = blockIdx.y, jt = blockIdx.x;
    int tid = threadIdx.x, lane = tid & 31;
    int j = jt*256 + tid;

    // qs2[hd*8 + p*2 + half] = q[b][2p+half][hd]  (i-pairs packed for FMA2)
    __shared__ __align__(16) float qs2[2048];
    __shared__ float den_s[32];

#pragma unroll
    for (int r = 0; r < 8; r++) {
        int u = r*256 + tid;
        int hd = u >> 3, p = (u >> 1) & 3, hf = u & 1;
        qs2[u] = g_q[(size_t)(b*8 + 2*p + hf)*256 + hd];
    }
    if (tid < 128) g_upd[b*2048 + jt*128 + tid] = 0.f;
    if (tid < 32) den_s[tid] = 0.f;
    __syncthreads();

    // dots accumulation: accp[p*4+h] = {dots[2p][h], dots[2p+1][h]} packed
    unsigned long long accp[16];
#pragma unroll
    for (int i = 0; i < 16; i++) accp[i] = 0ull;

    const float* kbase = g_kT + (size_t)b*256*4096 + j;
#pragma unroll
    for (int h = 0; h < 4; h++) {
#pragma unroll 8
        for (int d = 0; d < 64; d++) {
            int hd = h*64 + d;
            float kv = kbase[(size_t)hd*4096];
            unsigned long long kp; PK2(kp, kv, kv);
            ulonglong2 qa = *(const ulonglong2*)&qs2[hd*8];      // p=0,1
            ulonglong2 qb = *(const ulonglong2*)&qs2[hd*8 + 4];  // p=2,3
            FMA2(accp[0*4 + h], kp, qa.x, accp[0*4 + h]);
            FMA2(accp[1*4 + h], kp, qa.y, accp[1*4 + h]);
            FMA2(accp[2*4 + h], kp, qb.x, accp[2*4 + h]);
            FMA2(accp[3*4 + h], kp, qb.y, accp[3*4 + h]);
        }
    }

    float e[32];
#pragma unroll
    for (int p = 0; p < 4; p++)
#pragma unroll
        for (int h = 0; h < 4; h++)
            UPK2(e[(2*p)*4 + h], e[(2*p+1)*4 + h], accp[p*4 + h]);

    float mx = e[0];
#pragma unroll
    for (int i = 1; i < 32; i++) mx = fmaxf(mx, e[i]);
    float ssum = 0.f;
#pragma unroll
    for (int i = 0; i < 32; i++) { e[i] = __expf(e[i] - mx); ssum += e[i]; }
    float inv = 1.f / ssum;
#pragma unroll
    for (int i = 0; i < 32; i++) e[i] *= inv;

    // per-ih denominators: warp-reduce then smem/global atomics
#pragma unroll
    for (int i = 0; i < 32; i++) {
        float v = e[i];
        v += __shfl_xor_sync(0xffffffffu, v, 1);
        v += __shfl_xor_sync(0xffffffffu, v, 2);
        v += __shfl_xor_sync(0xffffffffu, v, 4);
        v += __shfl_xor_sync(0xffffffffu, v, 8);
        v += __shfl_xor_sync(0xffffffffu, v, 16);
        if (lane == 0) atomicAdd(&den_s[i], v);
    }
    __syncthreads();
    if (tid < 32) atomicAdd(&g_denom[b*32 + tid], den_s[tid]);

    // coalesced writes: attn (pre-renorm) + head-mean outputs
#pragma unroll
    for (int ih = 0; ih < 32; ih++)
        g_attn[(size_t)(b*32 + ih)*NN + j] = e[ih];
#pragma unroll
    for (int i = 0; i < 8; i++) {
        float ms = 0.25f*(e[i*4] + e[i*4+1] + e[i*4+2] + e[i*4+3]);
        size_t o = (size_t)(b*8 + i)*NN + j;
        out_stack[o] = ms;
        if (out_last) out_last[o] = ms;
    }
}

// ---------------- updates = (attn/denom) @ v ----------------
__global__ void __launch_bounds__(256)
upd_kernel() {
    int chunk = blockIdx.x, h = blockIdx.y, b = blockIdx.z;
    int tid = threadIdx.x;
    int d = tid & 63, js = tid >> 6;
    __shared__ float at_s[8][128];
    __shared__ float dinv[8];
    if (tid < 8) dinv[tid] = 1.f / (g_denom[b*32 + tid*4 + h] + SUM_EPS);
    float acc[8];
#pragma unroll
    for (int i = 0; i < 8; i++) acc[i] = 0.f;
    int j0 = chunk * 1024;
    for (int sc = 0; sc < 8; sc++) {
        __syncthreads();
#pragma unroll
        for (int r = 0; r < 4; r++) {
            int idx = r*256 + tid; int i = idx >> 7, jc = idx & 127;
            at_s[i][jc] = g_attn[(size_t)(b*32 + i*4 + h)*NN + j0 + sc*128 + jc];
        }
        __syncthreads();
#pragma unroll 8
        for (int jj = 0; jj < 32; jj++) {
            int jl = jj*4 + js;
            float vv = g_v[(size_t)(b*NN + j0 + sc*128 + jl)*256 + h*64 + d];
#pragma unroll
            for (int i = 0; i < 8; i++) acc[i] += vv * at_s[i][jl];
        }
    }
#pragma unroll
    for (int i = 0; i < 8; i++)
        atomicAdd(&g_upd[(b*8 + i)*256 + h*64 + d], acc[i] * dinv[i]);
}

// ---------------- GRU cell (4 rows per block for weight reuse) ----------------
__global__ void __launch_bounds__(256)
gru_kernel(int it, const float* __restrict__ cond, float* __restrict__ out_slots,
           const float* __restrict__ bih, const float* __restrict__ bhh) {
    const float* hsrc = (it == 0) ? cond : (it == 1 ? g_slotsA : g_slotsB);
    float* dst = (it == 0) ? g_slotsA : (it == 1 ? g_slotsB : out_slots);
    int t = threadIdx.x;
    __shared__ float u_s[4][256], h_s[4][256];
#pragma unroll
    for (int r = 0; r < 4; r++) {
        int row = blockIdx.x*4 + r;
        u_s[r][t] = g_upd[row*256 + t];
        h_s[r][t] = hsrc[row*256 + t];
    }
    __syncthreads();
    float axr[4] = {0,0,0,0}, axz[4] = {0,0,0,0}, axn[4] = {0,0,0,0};
    float ahr[4] = {0,0,0,0}, ahz[4] = {0,0,0,0}, ahn[4] = {0,0,0,0};
#pragma unroll 2
    for (int dd = 0; dd < 256; dd++) {
        float wr = g_WihT[dd*768 + t],       wz = g_WihT[dd*768 + 256 + t];
        float wn = g_WihT[dd*768 + 512 + t];
        float vr = g_WhhT[dd*768 + t],       vz = g_WhhT[dd*768 + 256 + t];
        float vn = g_WhhT[dd*768 + 512 + t];
#pragma unroll
        for (int r = 0; r < 4; r++) {
            float u = u_s[r][dd], hh = h_s[r][dd];
            axr[r] += u*wr;  axz[r] += u*wz;  axn[r] += u*wn;
            ahr[r] += hh*vr; ahz[r] += hh*vz; ahn[r] += hh*vn;
        }
    }
    float br = bih[t], bz = bih[256 + t], bn = bih[512 + t];
    float cr = bhh[t], cz = bhh[256 + t], cn = bhh[512 + t];
#pragma unroll
    for (int r = 0; r < 4; r++) {
        float rg = 1.f / (1.f + __expf(-(axr[r] + ahr[r] + br + cr)));
        float zg = 1.f / (1.f + __expf(-(axz[r] + ahz[r] + bz + cz)));
        float ng = tanhf(axn[r] + bn + rg*(ahn[r] + cn));
        int row = blockIdx.x*4 + r;
        dst[row*256 + t] = (1.f - zg)*ng + zg*h_s[r][t];
    }
}

// ---------------- launch ----------------
extern "C" void kernel_launch(void* const* d_in, const int* in_sizes, int n_in,
                              void* d_out, int out_size) {
    (void)in_sizes; (void)n_in; (void)out_size;
    const float* x    = (const float*)d_in[0];
    const float* cond = (const float*)d_in[1];
    const float* lniw = (const float*)d_in[2];
    const float* lnib = (const float*)d_in[3];
    const float* lnsw = (const float*)d_in[4];
    const float* lnsb = (const float*)d_in[5];
    const float* Wq   = (const float*)d_in[6];
    const float* Wk   = (const float*)d_in[7];
    const float* Wv   = (const float*)d_in[8];
    const float* wih  = (const float*)d_in[9];
    const float* whh  = (const float*)d_in[10];
    const float* bih  = (const float*)d_in[11];
    const float* bhh  = (const float*)d_in[12];

    float* out       = (float*)d_out;
    float* out_slots = out;                       // [64,8,256]
    float* out_last  = out + 131072;              // [64,8,4096]
    float* out_stack = out + 131072 + 2097152;    // [3,64,8,4096]

    cudaFuncSetAttribute(kv_hmma, cudaFuncAttributeMaxDynamicSharedMemorySize, KV_SMEM);

    prep_w<<<768, 256>>>(Wq, wih, whh);
    prep_b<<<512, 256>>>(Wk, Wv);
    kv_hmma<<<2048, 256, KV_SMEM>>>(x, lniw, lnib);

    for (int it = 0; it < 3; it++) {
        slot_q<<<64, 256>>>(it, cond, lnsw, lnsb);
        dots_softmax<<<dim3(16, 64), 256>>>(out_stack + (size_t)it*2097152,
                                            (it == 2) ? out_last : (float*)0);
        upd_kernel<<<dim3(4, 4, 64), 256>>>();
        gru_kernel<<<128, 256>>>(it, cond, out_slots, bih, bhh);
    }
}

// round 15
// speedup vs baseline: 2.4107x; 1.0856x over previous
#include <cuda_runtime.h>
#include <cuda_fp16.h>
#include <math.h>

#define NB 64
#define NN 4096
#define ROWS (NB*NN)          // 262144
#define SCALE 0.125f
#define LN_EPS 1e-5f
#define SUM_EPS 1e-8f

// ---------------- device scratch (no allocations allowed) ----------------
__device__ __align__(16) __half g_k16[(size_t)ROWS*256];   // [row][d] fp16 k
__device__ __align__(16) __half g_v16[(size_t)ROWS*256];   // [row][d] fp16 v
__device__ __align__(16) __half g_attn16[(size_t)NB*32*NN];// [b][ih][j] fp16
__device__ float g_WqT[256*256];
__device__ float g_WihT[256*768];
__device__ float g_WhhT[256*768];
__device__ float g_q[512*256];             // [(b*8+i)][h*64+d], pre-scaled
__device__ float g_denom[NB*32];
__device__ float g_upd[512*256];
__device__ float g_slotsA[512*256];
__device__ float g_slotsB[512*256];
// row-major fp16 image of Wk|Wv: [o in 0..511][k in 0..255]
__device__ __align__(16) unsigned short g_B_img[512*256];

// ---------------- f32x2 packed-FMA helpers (Blackwell) ----------------
#define PK2(d,x,y)   asm("mov.b64 %0, {%1,%2};"          : "=l"(d) : "f"(x), "f"(y))
#define UPK2(x,y,d)  asm("mov.b64 {%0,%1}, %2;"          : "=f"(x), "=f"(y) : "l"(d))
#define FMA2(d,a,b,c) asm("fma.rn.f32x2 %0, %1, %2, %3;" : "=l"(d) : "l"(a), "l"(b), "l"(c))

// ---------------- baseline-PTX tensor-core helpers (sm_80+) ----------------
__device__ __forceinline__ unsigned smem_u32(const void* p) {
    unsigned a;
    asm("{ .reg .u64 t; cvta.to.shared.u64 t, %1; cvt.u32.u64 %0, t; }" : "=r"(a) : "l"(p));
    return a;
}
#define LDSM4(r, a) \
    asm volatile("ldmatrix.sync.aligned.m8n8.x4.shared.b16 {%0,%1,%2,%3}, [%4];" \
        : "=r"((r)[0]), "=r"((r)[1]), "=r"((r)[2]), "=r"((r)[3]) : "r"(a))
#define MMA16816(d, a, b) \
    asm volatile("mma.sync.aligned.m16n8k16.row.col.f32.f16.f16.f32 " \
        "{%0,%1,%2,%3},{%4,%5,%6,%7},{%8,%9},{%0,%1,%2,%3};" \
        : "+f"((d)[0]), "+f"((d)[1]), "+f"((d)[2]), "+f"((d)[3]) \
        : "r"((a)[0]), "r"((a)[1]), "r"((a)[2]), "r"((a)[3]), "r"((b)[0]), "r"((b)[1]))
#define CP_ASYNC16(dst, src) \
    asm volatile("cp.async.cg.shared.global [%0], [%1], 16;" :: "r"(dst), "l"(src))
#define CP_COMMIT() asm volatile("cp.async.commit_group;" ::: "memory")
#define CP_WAIT1()  asm volatile("cp.async.wait_group 1;"  ::: "memory")
#define CP_WAIT0()  asm volatile("cp.async.wait_group 0;"  ::: "memory")

// ---------------- prep: transpose weights (Wq / GRU) ----------------
__global__ void prep_w(const float* __restrict__ Wq, const float* __restrict__ wih,
                       const float* __restrict__ whh) {
    int idx = blockIdx.x*256 + threadIdx.x;          // < 196608
    if (idx < 256*256) {
        int d = idx >> 8, o = idx & 255;
        g_WqT[idx] = Wq[o*256 + d];
    }
    {
        int d = idx / 768, o = idx - d*768;
        g_WihT[idx] = wih[o*256 + d];
        g_WhhT[idx] = whh[o*256 + d];
    }
}

// ---------------- prep: fp16 image of Wk|Wv (plain row-major) --------
__global__ void prep_b(const float* __restrict__ Wk, const float* __restrict__ Wv) {
    int o = blockIdx.x, k = threadIdx.x;
    float w = (o < 256) ? Wk[o*256 + k] : Wv[(o-256)*256 + k];
    g_B_img[o*256 + k] = __half_as_ushort(__float2half_rn(w));
}

// ---------------- HMMA K/V GEMM fragments (pure fp16) ----------
struct Frags {
    unsigned a0[4], a1[4];   // A (2 m-tiles)
    unsigned bh[8];          // B (2 n-sub-tiles)
};

__device__ __forceinline__ void load_frags(
    Frags& f, int ks, int half, unsigned buf,
    unsigned aBase0, unsigned aBase1, unsigned klA, unsigned xA,
    unsigned nB0row, unsigned nB1row, unsigned kbB, unsigned xB)
{
    unsigned kgA = (unsigned)(half*8 + ks)*2u + klA;
    unsigned aoff = ((kgA ^ xA) << 4);
    LDSM4(f.a0, aBase0 + aoff);
    LDSM4(f.a1, aBase1 + aoff);
    unsigned kgB = (unsigned)ks*2u + kbB;
    LDSM4(&f.bh[0], buf + nB0row + ((kgB ^ xB) << 4));
    LDSM4(&f.bh[4], buf + nB1row + ((kgB ^ xB) << 4));
}

__device__ __forceinline__ void do_mmas(float acc[2][4][4], const Frags& f) {
#pragma unroll
    for (int j = 0; j < 4; j++) {
        MMA16816(acc[0][j], f.a0, &f.bh[j*2]);
        MMA16816(acc[1][j], f.a1, &f.bh[j*2]);
    }
}

// ---------------- HMMA K/V GEMM: [262144,256] @ [256,512], fp16 ----
// CTA = 128 rows x 512 outputs, 2 CTAs/SM. LN stats computed inline.
// A fp16 resident; B streamed in 16 chunks of 16KB via cp.async dbl-buffer.
// Outputs written fp16 row-major to g_k16 / g_v16.
#define KV_SMEM 98304

__global__ void __launch_bounds__(256, 2)
kv_hmma(const float* __restrict__ x, const float* __restrict__ lw,
        const float* __restrict__ lb) {
    extern __shared__ char smem[];
    __shared__ float smu[128], srs[128];

    const unsigned sb  = smem_u32(smem);
    const unsigned sbB = sb + 65536u;
    int tid = threadIdx.x, wid = tid >> 5, lane = tid & 31;
    int m0 = blockIdx.x * 128;

    // ---- prefetch B chunk 0 into buffer 0 (16KB = 1024 float4) ----
    {
#pragma unroll
        for (int it = 0; it < 4; it++) {
            int u = tid + it*256;
            int o = u >> 4, g = u & 15;
            const char* src = (const char*)g_B_img + (size_t)o*512 + g*16;
            unsigned dst = sbB + o*256 + ((unsigned)(g ^ (o & 7)) << 4);
            CP_ASYNC16(dst, src);
        }
        CP_COMMIT();
    }

    // ---- inline LN stats: warp wid handles rows wid*16 .. wid*16+15 ----
#pragma unroll 2
    for (int r = 0; r < 16; r++) {
        int row = wid*16 + r;
        const float4* xr = (const float4*)(x + (size_t)(m0 + row)*256);
        float4 v0 = xr[lane*2], v1 = xr[lane*2 + 1];
        float s  = v0.x + v0.y + v0.z + v0.w + v1.x + v1.y + v1.z + v1.w;
        float ss = v0.x*v0.x + v0.y*v0.y + v0.z*v0.z + v0.w*v0.w
                 + v1.x*v1.x + v1.y*v1.y + v1.z*v1.z + v1.w*v1.w;
#pragma unroll
        for (int o = 16; o; o >>= 1) {
            s  += __shfl_xor_sync(0xffffffffu, s,  o);
            ss += __shfl_xor_sync(0xffffffffu, ss, o);
        }
        if (lane == 0) {
            float mu = s * (1.f/256.f);
            smu[row] = mu;
            srs[row] = rsqrtf(ss * (1.f/256.f) - mu*mu + LN_EPS);
        }
    }
    __syncthreads();

    // ---- load A with fused LN, fp16, swizzled ----
    {
        int cpair = tid & 127;            // column pair index
        int c2 = cpair * 2;
        int rbase = (tid >> 7) * 64;
        float w0 = lw[c2], w1 = lw[c2+1], bb0 = lb[c2], bb1 = lb[c2+1];
        unsigned gA = (unsigned)(cpair >> 2);
        unsigned boff = (unsigned)(cpair & 3) * 4u;
#pragma unroll 4
        for (int r = 0; r < 64; r++) {
            int row = rbase + r;
            float2 xv = *(const float2*)&x[(size_t)(m0 + row)*256 + c2];
            float mu = smu[row], rs = srs[row];
            float v0 = (xv.x - mu)*rs*w0 + bb0;
            float v1 = (xv.y - mu)*rs*w1 + bb1;
            unsigned hp = (unsigned)__half_as_ushort(__float2half_rn(v0)) |
                          ((unsigned)__half_as_ushort(__float2half_rn(v1)) << 16);
            unsigned phys = (unsigned)row*512u + ((gA ^ (unsigned)(row & 7)) << 4) + boff;
            *(unsigned*)(smem + phys) = hp;
        }
    }

    // ---- warp tiling: 4 M-warps x 2 N-warps, warp tile m32 x n32 ----
    int mw = wid >> 1, nw = wid & 1;
    int rA0 = mw*32 + (lane & 15);
    int rA1 = rA0 + 16;
    unsigned klA = (unsigned)(lane >> 4);
    unsigned xA = (unsigned)(rA0 & 7);
    unsigned aBase0 = sb + (unsigned)rA0*512u;
    unsigned aBase1 = sb + (unsigned)rA1*512u;

    int nB0 = nw*32 + (lane & 7) + ((lane >> 4) & 1)*8;
    int nB1 = nB0 + 16;
    unsigned nB0row = (unsigned)nB0*256u;
    unsigned nB1row = (unsigned)nB1*256u;
    unsigned kbB = (unsigned)((lane >> 3) & 1);
    unsigned xB = (unsigned)(nB0 & 7);

    float acc[2][4][4];
#pragma unroll
    for (int i = 0; i < 2; i++)
#pragma unroll
        for (int j = 0; j < 4; j++)
#pragma unroll
            for (int q = 0; q < 4; q++) acc[i][j][q] = 0.f;

    for (int c = 0; c < 16; c++) {
        if (c + 1 < 16) {
            int nbn = (c + 1) >> 1, halfn = (c + 1) & 1;
            unsigned bufn = sbB + (unsigned)((c + 1) & 1)*16384u;
#pragma unroll
            for (int it = 0; it < 4; it++) {
                int u = tid + it*256;
                int o = u >> 4, g = u & 15;
                const char* src = (const char*)g_B_img
                    + (size_t)(nbn*64 + o)*512 + halfn*256 + g*16;
                unsigned dst = bufn + o*256 + ((unsigned)(g ^ (o & 7)) << 4);
                CP_ASYNC16(dst, src);
            }
            CP_COMMIT();
            CP_WAIT1();
        } else {
            CP_WAIT0();
        }
        __syncthreads();

        unsigned buf = sbB + (unsigned)(c & 1)*16384u;
        int half = c & 1;

        Frags fr0, fr1;
        load_frags(fr0, 0, half, buf, aBase0, aBase1, klA, xA,
                   nB0row, nB1row, kbB, xB);
#pragma unroll
        for (int ks = 0; ks < 8; ks++) {
            Frags& cur = (ks & 1) ? fr1 : fr0;
            Frags& nxt = (ks & 1) ? fr0 : fr1;
            if (ks < 7)
                load_frags(nxt, ks + 1, half, buf, aBase0, aBase1, klA, xA,
                           nB0row, nB1row, kbB, xB);
            do_mmas(acc, cur);
        }

        if (c & 1) {
            int nbidx = c >> 1;
#pragma unroll
            for (int i = 0; i < 2; i++) {
#pragma unroll
                for (int j = 0; j < 4; j++) {
                    int row = m0 + mw*32 + i*16 + (lane >> 2);
                    int col = nbidx*64 + nw*32 + j*8 + (lane & 3)*2;
                    __half2 h0 = __floats2half2_rn(acc[i][j][0], acc[i][j][1]);
                    __half2 h1 = __floats2half2_rn(acc[i][j][2], acc[i][j][3]);
                    if (nbidx < 4) {
                        *(__half2*)&g_k16[(size_t)row*256 + col]       = h0;
                        *(__half2*)&g_k16[(size_t)(row + 8)*256 + col] = h1;
                    } else {
                        int vc = col - 256;
                        *(__half2*)&g_v16[(size_t)row*256 + vc]       = h0;
                        *(__half2*)&g_v16[(size_t)(row + 8)*256 + vc] = h1;
                    }
                    acc[i][j][0] = acc[i][j][1] = acc[i][j][2] = acc[i][j][3] = 0.f;
                }
            }
        }
        __syncthreads();
    }
}

// ---------------- slot LN + q projection (+ zero denom) ----------------
__global__ void __launch_bounds__(256)
slot_q(int it, const float* __restrict__ cond,
       const float* __restrict__ lw, const float* __restrict__ lb) {
    const float* src = (it == 0) ? cond : (it == 1 ? g_slotsA : g_slotsB);
    int b = blockIdx.x, t = threadIdx.x, wid = t >> 5, lane = t & 31;

    __shared__ float sn[8][256];
    __shared__ float wt[32][256];

    const float4* row = (const float4*)(src + (size_t)(b*8 + wid)*256);
    float4 v0 = row[lane], v1 = row[lane + 32];
    float s  = v0.x + v0.y + v0.z + v0.w + v1.x + v1.y + v1.z + v1.w;
    float ss = v0.x*v0.x + v0.y*v0.y + v0.z*v0.z + v0.w*v0.w
             + v1.x*v1.x + v1.y*v1.y + v1.z*v1.z + v1.w*v1.w;
#pragma unroll
    for (int o = 16; o; o >>= 1) {
        s  += __shfl_xor_sync(0xffffffffu, s,  o);
        ss += __shfl_xor_sync(0xffffffffu, ss, o);
    }
    float mu = s * (1.f/256.f);
    float rs = rsqrtf(ss * (1.f/256.f) - mu*mu + LN_EPS);
#pragma unroll
    for (int i = 0; i < 2; i++) {
        float4 xv = i ? v1 : v0;
        int c = (lane + 32*i) * 4;
        float4 w4 = *(const float4*)&lw[c];
        float4 b4 = *(const float4*)&lb[c];
        sn[wid][c+0] = (xv.x - mu)*rs*w4.x + b4.x;
        sn[wid][c+1] = (xv.y - mu)*rs*w4.y + b4.y;
        sn[wid][c+2] = (xv.z - mu)*rs*w4.z + b4.z;
        sn[wid][c+3] = (xv.w - mu)*rs*w4.w + b4.w;
    }
    if (t < 32) g_denom[b*32 + t] = 0.f;
    __syncthreads();

    float acc[8] = {0,0,0,0,0,0,0,0};
    for (int d0 = 0; d0 < 256; d0 += 32) {
        __syncthreads();
#pragma unroll
        for (int i = 0; i < 8; i++) {
            int u = t + i*256;
            int dd = u >> 6, g = u & 63;
            *(float4*)&wt[dd][g*4] = *(const float4*)&g_WqT[(d0 + dd)*256 + g*4];
        }
        __syncthreads();
#pragma unroll 4
        for (int dd = 0; dd < 32; dd++) {
            float w = wt[dd][t];
#pragma unroll
            for (int r = 0; r < 8; r++) acc[r] += sn[r][d0 + dd] * w;
        }
    }
#pragma unroll
    for (int r = 0; r < 8; r++) g_q[(size_t)(b*8 + r)*256 + t] = acc[r] * SCALE;
}

// ---------------- dots + softmax: thread-per-j, fp16 k, LDG.128 --------
// grid (16, 64): block handles j in [jt*256, jt*256+256) of batch b.
__global__ void __launch_bounds__(256)
dots_softmax(float* __restrict__ out_stack, float* __restrict__ out_last) {
    int b = blockIdx.y, jt = blockIdx.x;
    int tid = threadIdx.x, lane = tid & 31;
    int j = jt*256 + tid;

    // qs2[hd*8 + p*2 + half] = q[b][2p+half][hd]  (i-pairs packed for FMA2)
    __shared__ __align__(16) float qs2[2048];
    __shared__ float den_s[32];

#pragma unroll
    for (int r = 0; r < 8; r++) {
        int u = r*256 + tid;
        int hd = u >> 3, p = (u >> 1) & 3, hf = u & 1;
        qs2[u] = g_q[(size_t)(b*8 + 2*p + hf)*256 + hd];
    }
    if (tid < 128) g_upd[b*2048 + jt*128 + tid] = 0.f;
    if (tid < 32) den_s[tid] = 0.f;
    __syncthreads();

    // dots accumulation: accp[p*4+h] = {dots[2p][h], dots[2p+1][h]} packed
    unsigned long long accp[16];
#pragma unroll
    for (int i = 0; i < 16; i++) accp[i] = 0ull;

    const __half* krow = g_k16 + (size_t)(b*NN + j)*256;
#pragma unroll 4
    for (int hd0 = 0; hd0 < 256; hd0 += 8) {
        uint4 kq = *(const uint4*)(krow + hd0);
        int h = hd0 >> 6;
#pragma unroll
        for (int u = 0; u < 4; u++) {
            unsigned kk = (&kq.x)[u];
            float2 kf = __half22float2(*(const __half2*)&kk);
            int hd = hd0 + u*2;
            unsigned long long kpx, kpy;
            PK2(kpx, kf.x, kf.x);
            PK2(kpy, kf.y, kf.y);
            ulonglong2 qa = *(const ulonglong2*)&qs2[hd*8];
            ulonglong2 qb = *(const ulonglong2*)&qs2[hd*8 + 4];
            FMA2(accp[0  + h], kpx, qa.x, accp[0  + h]);
            FMA2(accp[4  + h], kpx, qa.y, accp[4  + h]);
            FMA2(accp[8  + h], kpx, qb.x, accp[8  + h]);
            FMA2(accp[12 + h], kpx, qb.y, accp[12 + h]);
            ulonglong2 qc = *(const ulonglong2*)&qs2[(hd+1)*8];
            ulonglong2 qd = *(const ulonglong2*)&qs2[(hd+1)*8 + 4];
            FMA2(accp[0  + h], kpy, qc.x, accp[0  + h]);
            FMA2(accp[4  + h], kpy, qc.y, accp[4  + h]);
            FMA2(accp[8  + h], kpy, qd.x, accp[8  + h]);
            FMA2(accp[12 + h], kpy, qd.y, accp[12 + h]);
        }
    }

    float e[32];
#pragma unroll
    for (int p = 0; p < 4; p++)
#pragma unroll
        for (int h = 0; h < 4; h++)
            UPK2(e[(2*p)*4 + h], e[(2*p+1)*4 + h], accp[p*4 + h]);

    float mx = e[0];
#pragma unroll
    for (int i = 1; i < 32; i++) mx = fmaxf(mx, e[i]);
    float ssum = 0.f;
#pragma unroll
    for (int i = 0; i < 32; i++) { e[i] = __expf(e[i] - mx); ssum += e[i]; }
    float inv = 1.f / ssum;
#pragma unroll
    for (int i = 0; i < 32; i++) e[i] *= inv;

    // per-ih denominators: warp-reduce then smem/global atomics
#pragma unroll
    for (int i = 0; i < 32; i++) {
        float v = e[i];
        v += __shfl_xor_sync(0xffffffffu, v, 1);
        v += __shfl_xor_sync(0xffffffffu, v, 2);
        v += __shfl_xor_sync(0xffffffffu, v, 4);
        v += __shfl_xor_sync(0xffffffffu, v, 8);
        v += __shfl_xor_sync(0xffffffffu, v, 16);
        if (lane == 0) atomicAdd(&den_s[i], v);
    }
    __syncthreads();
    if (tid < 32) atomicAdd(&g_denom[b*32 + tid], den_s[tid]);

    // coalesced writes: attn fp16 (pre-renorm) + head-mean outputs fp32
#pragma unroll
    for (int ih = 0; ih < 32; ih++)
        g_attn16[(size_t)(b*32 + ih)*NN + j] = __float2half_rn(e[ih]);
#pragma unroll
    for (int i = 0; i < 8; i++) {
        float ms = 0.25f*(e[i*4] + e[i*4+1] + e[i*4+2] + e[i*4+3]);
        size_t o = (size_t)(b*8 + i)*NN + j;
        out_stack[o] = ms;
        if (out_last) out_last[o] = ms;
    }
}

// ---------------- updates = (attn/denom) @ v  (fp16 v, packed FMA2) --------
__global__ void __launch_bounds__(256)
upd_kernel() {
    int chunk = blockIdx.x, h = blockIdx.y, b = blockIdx.z;
    int tid = threadIdx.x;
    int d2 = tid & 31;            // half2 col: d = 2*d2, 2*d2+1
    int js = tid >> 5;            // 0..7 (per-warp constant)
    __shared__ float at_s[8][128];
    __shared__ float dinv[8];
    if (tid < 8) dinv[tid] = 1.f / (g_denom[b*32 + tid*4 + h] + SUM_EPS);

    unsigned long long acc2[8];
#pragma unroll
    for (int i = 0; i < 8; i++) acc2[i] = 0ull;

    int j0 = chunk * 1024;
    for (int sc = 0; sc < 8; sc++) {
        __syncthreads();
#pragma unroll
        for (int r = 0; r < 4; r++) {
            int idx = r*256 + tid; int i = idx >> 7, jc = idx & 127;
            at_s[i][jc] = __half2float(
                g_attn16[(size_t)(b*32 + i*4 + h)*NN + j0 + sc*128 + jc]);
        }
        __syncthreads();
#pragma unroll 4
        for (int jj = 0; jj < 16; jj++) {
            int jl = jj*8 + js;
            __half2 vh = *(const __half2*)&g_v16[
                (size_t)(b*NN + j0 + sc*128 + jl)*256 + h*64 + d2*2];
            float2 vf = __half22float2(vh);
            unsigned long long vp; PK2(vp, vf.x, vf.y);
#pragma unroll
            for (int i = 0; i < 8; i++) {
                float at = at_s[i][jl];
                unsigned long long ap; PK2(ap, at, at);
                FMA2(acc2[i], vp, ap, acc2[i]);
            }
        }
    }
#pragma unroll
    for (int i = 0; i < 8; i++) {
        float a0, a1; UPK2(a0, a1, acc2[i]);
        float* dst = &g_upd[(b*8 + i)*256 + h*64 + d2*2];
        atomicAdd(dst,     a0 * dinv[i]);
        atomicAdd(dst + 1, a1 * dinv[i]);
    }
}

// ---------------- GRU cell (4 rows per block for weight reuse) ----------------
__global__ void __launch_bounds__(256)
gru_kernel(int it, const float* __restrict__ cond, float* __restrict__ out_slots,
           const float* __restrict__ bih, const float* __restrict__ bhh) {
    const float* hsrc = (it == 0) ? cond : (it == 1 ? g_slotsA : g_slotsB);
    float* dst = (it == 0) ? g_slotsA : (it == 1 ? g_slotsB : out_slots);
    int t = threadIdx.x;
    __shared__ float u_s[4][256], h_s[4][256];
#pragma unroll
    for (int r = 0; r < 4; r++) {
        int row = blockIdx.x*4 + r;
        u_s[r][t] = g_upd[row*256 + t];
        h_s[r][t] = hsrc[row*256 + t];
    }
    __syncthreads();
    float axr[4] = {0,0,0,0}, axz[4] = {0,0,0,0}, axn[4] = {0,0,0,0};
    float ahr[4] = {0,0,0,0}, ahz[4] = {0,0,0,0}, ahn[4] = {0,0,0,0};
#pragma unroll 2
    for (int dd = 0; dd < 256; dd++) {
        float wr = g_WihT[dd*768 + t],       wz = g_WihT[dd*768 + 256 + t];
        float wn = g_WihT[dd*768 + 512 + t];
        float vr = g_WhhT[dd*768 + t],       vz = g_WhhT[dd*768 + 256 + t];
        float vn = g_WhhT[dd*768 + 512 + t];
#pragma unroll
        for (int r = 0; r < 4; r++) {
            float u = u_s[r][dd], hh = h_s[r][dd];
            axr[r] += u*wr;  axz[r] += u*wz;  axn[r] += u*wn;
            ahr[r] += hh*vr; ahz[r] += hh*vz; ahn[r] += hh*vn;
        }
    }
    float br = bih[t], bz = bih[256 + t], bn = bih[512 + t];
    float cr = bhh[t], cz = bhh[256 + t], cn = bhh[512 + t];
#pragma unroll
    for (int r = 0; r < 4; r++) {
        float rg = 1.f / (1.f + __expf(-(axr[r] + ahr[r] + br + cr)));
        float zg = 1.f / (1.f + __expf(-(axz[r] + ahz[r] + bz + cz)));
        float ng = tanhf(axn[r] + bn + rg*(ahn[r] + cn));
        int row = blockIdx.x*4 + r;
        dst[row*256 + t] = (1.f - zg)*ng + zg*h_s[r][t];
    }
}

// ---------------- launch ----------------
extern "C" void kernel_launch(void* const* d_in, const int* in_sizes, int n_in,
                              void* d_out, int out_size) {
    (void)in_sizes; (void)n_in; (void)out_size;
    const float* x    = (const float*)d_in[0];
    const float* cond = (const float*)d_in[1];
    const float* lniw = (const float*)d_in[2];
    const float* lnib = (const float*)d_in[3];
    const float* lnsw = (const float*)d_in[4];
    const float* lnsb = (const float*)d_in[5];
    const float* Wq   = (const float*)d_in[6];
    const float* Wk   = (const float*)d_in[7];
    const float* Wv   = (const float*)d_in[8];
    const float* wih  = (const float*)d_in[9];
    const float* whh  = (const float*)d_in[10];
    const float* bih  = (const float*)d_in[11];
    const float* bhh  = (const float*)d_in[12];

    float* out       = (float*)d_out;
    float* out_slots = out;                       // [64,8,256]
    float* out_last  = out + 131072;              // [64,8,4096]
    float* out_stack = out + 131072 + 2097152;    // [3,64,8,4096]

    cudaFuncSetAttribute(kv_hmma, cudaFuncAttributeMaxDynamicSharedMemorySize, KV_SMEM);

    prep_w<<<768, 256>>>(Wq, wih, whh);
    prep_b<<<512, 256>>>(Wk, Wv);
    kv_hmma<<<2048, 256, KV_SMEM>>>(x, lniw, lnib);

    for (int it = 0; it < 3; it++) {
        slot_q<<<64, 256>>>(it, cond, lnsw, lnsb);
        dots_softmax<<<dim3(16, 64), 256>>>(out_stack + (size_t)it*2097152,
                                            (it == 2) ? out_last : (float*)0);
        upd_kernel<<<dim3(4, 4, 64), 256>>>();
        gru_kernel<<<128, 256>>>(it, cond, out_slots, bih, bhh);
    }
}